// round 15
// baseline (speedup 1.0000x reference)
#include <cuda_runtime.h>
#include <cuda_bf16.h>
#include <cuda_fp16.h>
#include <math.h>
#include <cstdint>

// ---------------------------------------------------------------------------
// Problem constants
// ---------------------------------------------------------------------------
#define BB 4
#define TT 128
#define DD 256
#define FF_ 1024
#define NH 8
#define HD_ATT 32
#define VOCAB 32000
#define MD 128
#define IFACE 516       // MH*(4*HD+1)
#define CDIM 384        // D + MD
#define BT (BB*TT)      // 512

// ---------------------------------------------------------------------------
// Scratch (device globals; no allocation allowed)
// ---------------------------------------------------------------------------
__device__ float g_x  [BT*DD];
__device__ float g_qkv[BT*3*DD];
__device__ float g_att[BT*DD];
__device__ float g_ff [BT*FF_];
__device__ float g_Hif[BT*IFACE];
__device__ __align__(16) __half g_ch[BT*CDIM];      // concat [lnf(x) | rv] fp16
__device__ __align__(16) __half g_wlh[CDIM*VOCAB];  // W_logits pre-converted fp16

// ---------------------------------------------------------------------------
// W_logits fp32 -> fp16 (one-time per launch; no deps, runs first)
// ---------------------------------------------------------------------------
__global__ void wconv_kernel(const float* __restrict__ W, __half* __restrict__ Wh)
{
    long i = ((long)blockIdx.x * 256 + threadIdx.x) * 4;
    float4 v = *reinterpret_cast<const float4*>(W + i);
    __half2 h0 = __floats2half2_rn(v.x, v.y);
    __half2 h1 = __floats2half2_rn(v.z, v.w);
    uint2 u;
    u.x = *reinterpret_cast<unsigned*>(&h0);
    u.y = *reinterpret_cast<unsigned*>(&h1);
    *reinterpret_cast<uint2*>(Wh + i) = u;
}

// ---------------------------------------------------------------------------
// Embedding
// ---------------------------------------------------------------------------
__global__ void embed_kernel(const int* __restrict__ seq,
                             const float* __restrict__ tok,
                             const float* __restrict__ pos,
                             float* __restrict__ x)
{
    int bt = blockIdx.x;
    int d  = threadIdx.x;
    int t  = bt & (TT-1);
    x[bt*DD + d] = tok[(long)seq[bt]*DD + d] + pos[t*DD + d];
}

// ---------------------------------------------------------------------------
// Final LayerNorm -> fp16 into g_ch left half (stride CDIM)
// ---------------------------------------------------------------------------
__global__ void lnf_half_kernel(const float* __restrict__ x,
                                const float* __restrict__ g,
                                const float* __restrict__ b,
                                __half* __restrict__ ch)
{
    int row = blockIdx.x;
    int tid = threadIdx.x;
    __shared__ float red[8];
    float v = x[row*DD + tid];
    float s = v;
    #pragma unroll
    for (int k = 16; k; k >>= 1) s += __shfl_xor_sync(0xffffffffu, s, k);
    if ((tid & 31) == 0) red[tid >> 5] = s;
    __syncthreads();
    float mean = 0.f;
    #pragma unroll
    for (int i = 0; i < 8; i++) mean += red[i];
    mean *= (1.f/256.f);
    __syncthreads();
    float d = v - mean;
    float s2 = d*d;
    #pragma unroll
    for (int k = 16; k; k >>= 1) s2 += __shfl_xor_sync(0xffffffffu, s2, k);
    if ((tid & 31) == 0) red[tid >> 5] = s2;
    __syncthreads();
    float var = 0.f;
    #pragma unroll
    for (int i = 0; i < 8; i++) var += red[i];
    var *= (1.f/256.f);
    ch[row*CDIM + tid] = __float2half(d * rsqrtf(var + 1e-5f) * g[tid] + b[tid]);
}

// ---------------------------------------------------------------------------
// TF32 / cp.async helpers
// ---------------------------------------------------------------------------
__device__ __forceinline__ unsigned f2tf32(float x) {
    unsigned r;
    asm("cvt.rna.tf32.f32 %0, %1;" : "=r"(r) : "f"(x));
    return r;
}
__device__ __forceinline__ void mma_tf32(float* c, const unsigned* a, const unsigned* b) {
    asm volatile(
        "mma.sync.aligned.m16n8k8.row.col.f32.tf32.tf32.f32 "
        "{%0,%1,%2,%3}, {%4,%5,%6,%7}, {%8,%9}, {%0,%1,%2,%3};"
        : "+f"(c[0]), "+f"(c[1]), "+f"(c[2]), "+f"(c[3])
        : "r"(a[0]), "r"(a[1]), "r"(a[2]), "r"(a[3]),
          "r"(b[0]), "r"(b[1]));
}
__device__ __forceinline__ uint32_t smem_u32(const void* p) {
    uint32_t a;
    asm("{ .reg .u64 t; cvta.to.shared.u64 t, %1; cvt.u32.u64 %0, t; }" : "=r"(a) : "l"(p));
    return a;
}
__device__ __forceinline__ void cp_async16(uint32_t saddr, const void* gptr) {
    asm volatile("cp.async.cg.shared.global [%0], [%1], 16;" :: "r"(saddr), "l"(gptr));
}
__device__ __forceinline__ void cp_commit() {
    asm volatile("cp.async.commit_group;" ::: "memory");
}
__device__ __forceinline__ void cp_wait3() {
    asm volatile("cp.async.wait_group 3;" ::: "memory");
}
__device__ __forceinline__ void cp_wait2() {
    asm volatile("cp.async.wait_group 2;" ::: "memory");
}
__device__ __forceinline__ void cp_wait1() {
    asm volatile("cp.async.wait_group 1;" ::: "memory");
}
__device__ __forceinline__ void cp_wait0() {
    asm volatile("cp.async.wait_group 0;" ::: "memory");
}
__device__ __forceinline__ void cp_wait_n(int n) {
    if (n >= 3) cp_wait3();
    else if (n == 2) cp_wait2();
    else if (n == 1) cp_wait1();
    else cp_wait0();
}

// ---------------------------------------------------------------------------
// FP16 mma helpers (logits GEMM)
// ---------------------------------------------------------------------------
__device__ __forceinline__ void ldsm_x4(unsigned* r, uint32_t addr) {
    asm volatile("ldmatrix.sync.aligned.m8n8.x4.shared.b16 {%0,%1,%2,%3}, [%4];"
        : "=r"(r[0]), "=r"(r[1]), "=r"(r[2]), "=r"(r[3]) : "r"(addr));
}
__device__ __forceinline__ void ldsm_x4_t(unsigned* r, uint32_t addr) {
    asm volatile("ldmatrix.sync.aligned.m8n8.x4.trans.shared.b16 {%0,%1,%2,%3}, [%4];"
        : "=r"(r[0]), "=r"(r[1]), "=r"(r[2]), "=r"(r[3]) : "r"(addr));
}
__device__ __forceinline__ void mma_f16(float* c, const unsigned* a, unsigned b0, unsigned b1) {
    asm volatile(
        "mma.sync.aligned.m16n8k16.row.col.f32.f16.f16.f32 "
        "{%0,%1,%2,%3}, {%4,%5,%6,%7}, {%8,%9}, {%0,%1,%2,%3};"
        : "+f"(c[0]), "+f"(c[1]), "+f"(c[2]), "+f"(c[3])
        : "r"(a[0]), "r"(a[1]), "r"(a[2]), "r"(a[3]),
          "r"(b0), "r"(b1));
}

// ---------------------------------------------------------------------------
// FP16 logits GEMM, cp.async 2-stage, 128m x 64n block tile, 8 warps (4m x 2n),
// warp tile 32x32 -> acc 32 regs -> 3 blocks/SM.  Grid (4, 500), m fastest.
// Bh row stride 72 halves = 144 B (16B-divisible for cp.async; ldsm.trans
// banks 4r%32 -> conflict-free).
// ---------------------------------------------------------------------------
__global__ __launch_bounds__(256, 3) void logits_f16_kernel(
    const __half* __restrict__ A,
    const __half* __restrict__ Bh_g,
    float* __restrict__ C,
    const float* __restrict__ bias)
{
    __shared__ __half Ah[2][128][40];
    __shared__ __half Bh[2][32][72];

    const int tid  = threadIdx.x;
    const int lane = tid & 31;
    const int wid  = tid >> 5;
    const int wm   = (wid & 3) * 32;     // 4 m-warps
    const int wn   = (wid >> 2) * 32;    // 2 n-warps
    const int m0   = blockIdx.x * 128;   // m fastest: 4 m-blocks share B n-strip
    const int n0   = blockIdx.y * 64;

    const uint32_t ahBase = smem_u32(&Ah[0][0][0]);
    const uint32_t bhBase = smem_u32(&Bh[0][0][0]);

    // A tile: 128 rows x 32 halves = 512 x 16B chunks; 2 per thread
    // B tile: 32 rows x 64 halves  = 256 x 16B chunks; 1 per thread
    auto fill = [&](int s, int k0) {
        #pragma unroll
        for (int i = 0; i < 2; i++) {
            int id = i*256 + tid;
            int r  = id >> 2;
            int c  = (id & 3) << 3;
            cp_async16(ahBase + (uint32_t)(((s*128 + r)*40 + c) << 1),
                       A + (long)(m0 + r)*CDIM + k0 + c);
        }
        {
            int r = tid >> 3;
            int c = (tid & 7) << 3;
            cp_async16(bhBase + (uint32_t)(((s*32 + r)*72 + c) << 1),
                       Bh_g + (long)(k0 + r)*VOCAB + n0 + c);
        }
        cp_commit();
    };

    float acc[8][4];
    #pragma unroll
    for (int i = 0; i < 8; i++)
        #pragma unroll
        for (int j = 0; j < 4; j++) acc[i][j] = 0.f;

    fill(0, 0);

    #pragma unroll 1
    for (int kt = 0; kt < CDIM/32; kt++) {
        const bool more = (kt + 1) < CDIM/32;
        if (more) fill((kt + 1) & 1, (kt + 1) * 32);
        if (more) cp_wait1(); else cp_wait0();
        __syncthreads();

        const int buf = kt & 1;
        #pragma unroll
        for (int ks = 0; ks < 32; ks += 16) {
            unsigned af[2][4], bf[2][4];
            #pragma unroll
            for (int mt = 0; mt < 2; mt++) {
                int row = wm + mt*16 + (lane & 15);
                int col = ks + ((lane & 16) >> 1);
                ldsm_x4(af[mt], smem_u32(&Ah[buf][row][col]));
            }
            #pragma unroll
            for (int pr = 0; pr < 2; pr++) {
                int row = ks + (lane & 15);
                int col = wn + pr*16 + ((lane & 16) >> 1);
                ldsm_x4_t(bf[pr], smem_u32(&Bh[buf][row][col]));
            }
            #pragma unroll
            for (int mt = 0; mt < 2; mt++)
                #pragma unroll
                for (int nt = 0; nt < 4; nt++)
                    mma_f16(acc[mt*4 + nt], af[mt],
                            bf[nt >> 1][(nt & 1)*2], bf[nt >> 1][(nt & 1)*2 + 1]);
        }
        __syncthreads();
    }

    const int g  = lane >> 2;
    const int tg = lane & 3;
    #pragma unroll
    for (int nt = 0; nt < 4; nt++) {
        int n = n0 + wn + nt*8 + 2*tg;
        float2 bz = *reinterpret_cast<const float2*>(bias + n);
        #pragma unroll
        for (int mt = 0; mt < 2; mt++) {
            int m = m0 + wm + mt*16 + g;
            float* c = acc[mt*4 + nt];
            *reinterpret_cast<float2*>(C + (long)m*VOCAB + n)     = make_float2(c[0]+bz.x, c[1]+bz.y);
            *reinterpret_cast<float2*>(C + (long)(m+8)*VOCAB + n) = make_float2(c[2]+bz.x, c[3]+bz.y);
        }
    }
}

// ---------------------------------------------------------------------------
// TF32 small GEMM, 2-stage cp.async pipeline, optional fused LayerNorm on A.
// 64x64 tile, BK=32, 4 warps.  (QKV / FF1 / iface — grids >= 72 blocks.)
// ---------------------------------------------------------------------------
template<bool GELU, bool LN>
__global__ __launch_bounds__(128) void tc_gemm(
    int N, int K,
    const float* __restrict__ A, int lda,
    const float* __restrict__ B, int ldb,
    float* __restrict__ C, int ldc,
    const float* __restrict__ bias,
    const float* __restrict__ residual,
    const float* __restrict__ ln_g,
    const float* __restrict__ ln_b)
{
    __shared__ float As[2][64][36];
    __shared__ float Bs[2][32][68];
    __shared__ float smean[64];
    __shared__ float srstd[64];
    __shared__ float sg[256];
    __shared__ float sb[256];

    const int tid  = threadIdx.x;
    const int lane = tid & 31;
    const int wid  = tid >> 5;
    const int wm   = (wid >> 1) * 32;
    const int wn   = (wid & 1) * 32;
    const int m0   = blockIdx.y * 64;
    const int n0   = blockIdx.x * 64;
    const int g    = lane >> 2;
    const int tg   = lane & 3;
    const int nt   = K >> 5;

    const uint32_t asBase = smem_u32(&As[0][0][0]);
    const uint32_t bsBase = smem_u32(&Bs[0][0][0]);

    const int a_r  = tid >> 3;
    const int a_c4 = (tid & 7) << 2;
    const int b_r  = tid >> 4;
    const int b_c4 = (tid & 15) << 2;

    auto fill = [&](int s, int k0) {
        #pragma unroll
        for (int i = 0; i < 4; i++) {
            int r = a_r + i*16;
            cp_async16(asBase + (uint32_t)(((s*64 + r)*36 + a_c4) << 2),
                       A + (long)(m0 + r)*lda + k0 + a_c4);
        }
        #pragma unroll
        for (int i = 0; i < 4; i++) {
            int r = b_r + i*8;
            if (n0 + b_c4 < N) {
                cp_async16(bsBase + (uint32_t)(((s*32 + r)*68 + b_c4) << 2),
                           B + (long)(k0 + r)*ldb + n0 + b_c4);
            } else {
                *reinterpret_cast<float4*>(&Bs[s][r][b_c4]) = make_float4(0.f,0.f,0.f,0.f);
            }
        }
        cp_commit();
    };

    fill(0, 0);

    if (LN) {
        int r  = tid >> 1;
        int hf = tid & 1;
        const float* rowp = A + (long)(m0 + r)*lda;
        float s = 0.f, s2 = 0.f;
        for (int i = hf*4; i < K; i += 8) {
            float4 u = *reinterpret_cast<const float4*>(rowp + i);
            s  += u.x + u.y + u.z + u.w;
            s2 += u.x*u.x + u.y*u.y + u.z*u.z + u.w*u.w;
        }
        s  += __shfl_xor_sync(0xffffffffu, s, 1);
        s2 += __shfl_xor_sync(0xffffffffu, s2, 1);
        if (!hf) {
            float inv = 1.f / (float)K;
            float mu  = s * inv;
            float var = s2 * inv - mu*mu;
            smean[r] = mu;
            srstd[r] = rsqrtf(var + 1e-5f);
        }
        if (tid < 64) {
            *reinterpret_cast<float4*>(&sg[tid*4]) = *reinterpret_cast<const float4*>(ln_g + tid*4);
        } else {
            int t = tid - 64;
            *reinterpret_cast<float4*>(&sb[t*4]) = *reinterpret_cast<const float4*>(ln_b + t*4);
        }
        __syncthreads();
    }

    float rs_[4], mrs_[4];
    if (LN) {
        #pragma unroll
        for (int q = 0; q < 4; q++) {
            int r = wm + q*8 + g;
            rs_[q]  = srstd[r];
            mrs_[q] = smean[r] * rs_[q];
        }
    }

    float acc[8][4];
    #pragma unroll
    for (int i = 0; i < 8; i++)
        #pragma unroll
        for (int j = 0; j < 4; j++) acc[i][j] = 0.f;

    #pragma unroll 1
    for (int kt = 0; kt < nt; kt++) {
        const bool more = (kt + 1) < nt;
        if (more) fill((kt + 1) & 1, (kt + 1) * 32);
        if (more) cp_wait1(); else cp_wait0();
        __syncthreads();

        const int buf = kt & 1;
        const int k0  = kt * 32;

        #pragma unroll
        for (int ks = 0; ks < 32; ks += 8) {
            unsigned af[2][4], bf[4][2];
            float gm0 = 0.f, gm4 = 0.f, bt0 = 0.f, bt4 = 0.f;
            if (LN) {
                gm0 = sg[k0 + ks + tg];   gm4 = sg[k0 + ks + tg + 4];
                bt0 = sb[k0 + ks + tg];   bt4 = sb[k0 + ks + tg + 4];
            }
            #pragma unroll
            for (int mt = 0; mt < 2; mt++) {
                int mr = wm + mt*16 + g;
                float r00 = As[buf][mr  ][ks + tg    ];
                float r10 = As[buf][mr+8][ks + tg    ];
                float r04 = As[buf][mr  ][ks + tg + 4];
                float r14 = As[buf][mr+8][ks + tg + 4];
                if (LN) {
                    float rsa = rs_[mt*2],   ma = mrs_[mt*2];
                    float rsb = rs_[mt*2+1], mb = mrs_[mt*2+1];
                    r00 = fmaf(fmaf(r00, rsa, -ma), gm0, bt0);
                    r10 = fmaf(fmaf(r10, rsb, -mb), gm0, bt0);
                    r04 = fmaf(fmaf(r04, rsa, -ma), gm4, bt4);
                    r14 = fmaf(fmaf(r14, rsb, -mb), gm4, bt4);
                }
                af[mt][0] = f2tf32(r00);
                af[mt][1] = f2tf32(r10);
                af[mt][2] = f2tf32(r04);
                af[mt][3] = f2tf32(r14);
            }
            #pragma unroll
            for (int nt2 = 0; nt2 < 4; nt2++) {
                int nc = wn + nt2*8 + g;
                bf[nt2][0] = f2tf32(Bs[buf][ks + tg    ][nc]);
                bf[nt2][1] = f2tf32(Bs[buf][ks + tg + 4][nc]);
            }
            #pragma unroll
            for (int mt = 0; mt < 2; mt++)
                #pragma unroll
                for (int nt2 = 0; nt2 < 4; nt2++)
                    mma_tf32(acc[mt*4 + nt2], af[mt], bf[nt2]);
        }
        __syncthreads();
    }

    #pragma unroll
    for (int nt2 = 0; nt2 < 4; nt2++) {
        int n = n0 + wn + nt2*8 + 2*tg;
        if (n < N) {
            float2 bz = make_float2(0.f, 0.f);
            if (bias) bz = *reinterpret_cast<const float2*>(bias + n);
            #pragma unroll
            for (int mt = 0; mt < 2; mt++) {
                int m = m0 + wm + mt*16 + g;
                float* c = acc[mt*4 + nt2];
                float v[4] = {c[0]+bz.x, c[1]+bz.y, c[2]+bz.x, c[3]+bz.y};
                if (GELU) {
                    #pragma unroll
                    for (int q = 0; q < 4; q++) {
                        float u = v[q];
                        float tt = 0.7978845608028654f * (u + 0.044715f*u*u*u);
                        v[q] = 0.5f*u*(1.f + tanhf(tt));
                    }
                }
                if (residual) {
                    float2 r0 = *reinterpret_cast<const float2*>(residual + (long)m*ldc + n);
                    float2 r1 = *reinterpret_cast<const float2*>(residual + (long)(m+8)*ldc + n);
                    v[0] += r0.x; v[1] += r0.y; v[2] += r1.x; v[3] += r1.y;
                }
                *reinterpret_cast<float2*>(C + (long)m*ldc + n)     = make_float2(v[0], v[1]);
                *reinterpret_cast<float2*>(C + (long)(m+8)*ldc + n) = make_float2(v[2], v[3]);
            }
        }
    }
}

// ---------------------------------------------------------------------------
// TF32 tiny-tile GEMM (Wo, FF2): 32x32 tile, BK=32, 4-stage cp.async.
// ---------------------------------------------------------------------------
__global__ __launch_bounds__(128) void tc_gemm_small(
    int N, int K,
    const float* __restrict__ A, int lda,
    const float* __restrict__ B, int ldb,
    float* __restrict__ C, int ldc,
    const float* __restrict__ bias,
    const float* __restrict__ residual)
{
    __shared__ float As[4][32][36];
    __shared__ float Bs[4][32][36];

    const int tid  = threadIdx.x;
    const int lane = tid & 31;
    const int wid  = tid >> 5;
    const int wm   = (wid >> 1) * 16;
    const int wn   = (wid & 1) * 16;
    const int m0   = blockIdx.y * 32;
    const int n0   = blockIdx.x * 32;
    const int g    = lane >> 2;
    const int tg   = lane & 3;
    const int nt   = K >> 5;

    const uint32_t asBase = smem_u32(&As[0][0][0]);
    const uint32_t bsBase = smem_u32(&Bs[0][0][0]);
    const int r_  = tid >> 3;
    const int c4  = (tid & 7) << 2;

    auto fill = [&](int s, int k0) {
        #pragma unroll
        for (int i = 0; i < 2; i++) {
            int r = r_ + i*16;
            cp_async16(asBase + (uint32_t)(((s*32 + r)*36 + c4) << 2),
                       A + (long)(m0 + r)*lda + k0 + c4);
            cp_async16(bsBase + (uint32_t)(((s*32 + r)*36 + c4) << 2),
                       B + (long)(k0 + r)*ldb + n0 + c4);
        }
        cp_commit();
    };

    const int pre = (nt < 3) ? nt : 3;
    for (int s = 0; s < pre; s++) fill(s, s*32);

    float acc[2][4];
    #pragma unroll
    for (int i = 0; i < 2; i++)
        #pragma unroll
        for (int j = 0; j < 4; j++) acc[i][j] = 0.f;

    #pragma unroll 1
    for (int kt = 0; kt < nt; kt++) {
        if (kt + 3 < nt) fill((kt + 3) & 3, (kt + 3) * 32);
        int ahead = nt - 1 - kt;
        cp_wait_n(ahead < 3 ? ahead : 3);
        __syncthreads();

        const int buf = kt & 3;
        #pragma unroll
        for (int ks = 0; ks < 32; ks += 8) {
            unsigned af[4], bf[2][2];
            af[0] = f2tf32(As[buf][wm + g    ][ks + tg    ]);
            af[1] = f2tf32(As[buf][wm + g + 8][ks + tg    ]);
            af[2] = f2tf32(As[buf][wm + g    ][ks + tg + 4]);
            af[3] = f2tf32(As[buf][wm + g + 8][ks + tg + 4]);
            #pragma unroll
            for (int nt2 = 0; nt2 < 2; nt2++) {
                int nc = wn + nt2*8 + g;
                bf[nt2][0] = f2tf32(Bs[buf][ks + tg    ][nc]);
                bf[nt2][1] = f2tf32(Bs[buf][ks + tg + 4][nc]);
            }
            #pragma unroll
            for (int nt2 = 0; nt2 < 2; nt2++)
                mma_tf32(acc[nt2], af, bf[nt2]);
        }
        __syncthreads();
    }

    #pragma unroll
    for (int nt2 = 0; nt2 < 2; nt2++) {
        int n = n0 + wn + nt2*8 + 2*tg;
        float2 bz = make_float2(0.f, 0.f);
        if (bias) bz = *reinterpret_cast<const float2*>(bias + n);
        int m = m0 + wm + g;
        float* c = acc[nt2];
        float v[4] = {c[0]+bz.x, c[1]+bz.y, c[2]+bz.x, c[3]+bz.y};
        if (residual) {
            float2 r0 = *reinterpret_cast<const float2*>(residual + (long)m*ldc + n);
            float2 r1 = *reinterpret_cast<const float2*>(residual + (long)(m+8)*ldc + n);
            v[0] += r0.x; v[1] += r0.y; v[2] += r1.x; v[3] += r1.y;
        }
        *reinterpret_cast<float2*>(C + (long)m*ldc + n)     = make_float2(v[0], v[1]);
        *reinterpret_cast<float2*>(C + (long)(m+8)*ldc + n) = make_float2(v[2], v[3]);
    }
}

// ---------------------------------------------------------------------------
// Causal attention: block = (head, batch, q-chunk of 8). 512 blocks.
// Ps stride 132 (16B-aligned rows) -> float4 reads in PV loop.
// ---------------------------------------------------------------------------
#define QC 8
__global__ __launch_bounds__(128) void attention_kernel(
    const float* __restrict__ qkv, float* __restrict__ att_out)
{
    __shared__ float Ks[TT][36];
    __shared__ float Vs[TT][32];
    __shared__ __align__(16) float Ps[QC][132];
    const int h  = blockIdx.x;
    const int b  = blockIdx.y;
    const int qc = blockIdx.z;
    const int tid = threadIdx.x;
    const float scale = 0.17677669529663687f;

    {
        const float* kp = qkv + (long)(b*TT + tid)*(3*DD) + DD + h*HD_ATT;
        const float* vp = kp + DD;
        #pragma unroll
        for (int d = 0; d < 32; d += 4) {
            *reinterpret_cast<float4*>(&Ks[tid][d]) = *reinterpret_cast<const float4*>(kp + d);
            *reinterpret_cast<float4*>(&Vs[tid][d]) = *reinterpret_cast<const float4*>(vp + d);
        }
    }
    __syncthreads();

    const int q = tid >> 4;
    const int j = tid & 15;
    const int qglob = qc*QC + q;

    float qv[32];
    {
        const float* qp = qkv + (long)(b*TT + qglob)*(3*DD) + h*HD_ATT;
        #pragma unroll
        for (int d = 0; d < 32; d += 4) {
            float4 t = *reinterpret_cast<const float4*>(qp + d);
            qv[d]=t.x; qv[d+1]=t.y; qv[d+2]=t.z; qv[d+3]=t.w;
        }
    }

    float s[8];
    float mmax = -1e30f;
    #pragma unroll
    for (int kk = 0; kk < 8; kk++) {
        int k = kk*16 + j;
        float acc = 0.f;
        #pragma unroll
        for (int d = 0; d < 32; d += 4) {
            float4 kv = *reinterpret_cast<const float4*>(&Ks[k][d]);
            acc += qv[d]*kv.x + qv[d+1]*kv.y + qv[d+2]*kv.z + qv[d+3]*kv.w;
        }
        s[kk] = (k <= qglob) ? acc*scale : -1e30f;
        mmax = fmaxf(mmax, s[kk]);
    }
    #pragma unroll
    for (int o = 1; o < 16; o <<= 1)
        mmax = fmaxf(mmax, __shfl_xor_sync(0xffffffffu, mmax, o));

    float l = 0.f;
    #pragma unroll
    for (int kk = 0; kk < 8; kk++) {
        float p = __expf(s[kk] - mmax);
        l += p;
        Ps[q][kk*16 + j] = p;
    }
    #pragma unroll
    for (int o = 1; o < 16; o <<= 1)
        l += __shfl_xor_sync(0xffffffffu, l, o);
    float linv = 1.f / l;
    __syncthreads();

    float ox = 0.f, oy = 0.f;
    #pragma unroll 4
    for (int k = 0; k < TT; k += 4) {
        float4 p4 = *reinterpret_cast<const float4*>(&Ps[q][k]);
        float2 v0 = *reinterpret_cast<const float2*>(&Vs[k  ][j*2]);
        float2 v1 = *reinterpret_cast<const float2*>(&Vs[k+1][j*2]);
        float2 v2 = *reinterpret_cast<const float2*>(&Vs[k+2][j*2]);
        float2 v3 = *reinterpret_cast<const float2*>(&Vs[k+3][j*2]);
        ox += p4.x*v0.x + p4.y*v1.x + p4.z*v2.x + p4.w*v3.x;
        oy += p4.x*v0.y + p4.y*v1.y + p4.z*v2.y + p4.w*v3.y;
    }
    float2 o2 = make_float2(ox*linv, oy*linv);
    *reinterpret_cast<float2*>(att_out + (long)(b*TT + qglob)*DD + h*HD_ATT + j*2) = o2;
}

// ---------------------------------------------------------------------------
// Memory scan (collapsed; see derivation R2).  fma.rn.f32x2 GEMV, 4 accs.
// ---------------------------------------------------------------------------
__global__ __launch_bounds__(320) void scan_kernel(
    const float* __restrict__ Hif,
    const float* __restrict__ W_iface,
    __half* __restrict__ ch)
{
    int b   = blockIdx.x;
    int tid = threadIdx.x;
    __shared__ __align__(16) float rv_s[MD];
    __shared__ float m_s[MD];
    __shared__ float if_s[260];

    unsigned long long w2[64];
    int gcol = 0;
    if (tid < 260) {
        gcol = (tid/65)*129 + 64 + (tid%65);
        #pragma unroll
        for (int k = 0; k < 64; k++) {
            float lo = W_iface[(long)(256 + 2*k    )*IFACE + gcol];
            float hi = W_iface[(long)(256 + 2*k + 1)*IFACE + gcol];
            asm("mov.b64 %0, {%1,%2};" : "=l"(w2[k]) : "f"(lo), "f"(hi));
        }
    }
    if (tid < MD) { rv_s[tid] = 0.f; m_s[tid] = 0.f; }
    __syncthreads();

    const unsigned long long* rv2 = reinterpret_cast<const unsigned long long*>(rv_s);

    for (int t = 0; t < TT; t++) {
        if (tid < MD)
            ch[(long)(b*TT + t)*CDIM + DD + tid] = __float2half(rv_s[tid]);
        if (tid < 260) {
            float hbase = Hif[(long)(b*TT + t)*IFACE + gcol];
            unsigned long long a0 = 0ull, a1 = 0ull, a2 = 0ull, a3 = 0ull;
            #pragma unroll
            for (int k = 0; k < 64; k += 4) {
                asm("fma.rn.f32x2 %0, %1, %2, %0;" : "+l"(a0) : "l"(rv2[k  ]), "l"(w2[k  ]));
                asm("fma.rn.f32x2 %0, %1, %2, %0;" : "+l"(a1) : "l"(rv2[k+1]), "l"(w2[k+1]));
                asm("fma.rn.f32x2 %0, %1, %2, %0;" : "+l"(a2) : "l"(rv2[k+2]), "l"(w2[k+2]));
                asm("fma.rn.f32x2 %0, %1, %2, %0;" : "+l"(a3) : "l"(rv2[k+3]), "l"(w2[k+3]));
            }
            float l0, h0, l1, h1, l2, h2, l3, h3;
            asm("mov.b64 {%0,%1}, %2;" : "=f"(l0), "=f"(h0) : "l"(a0));
            asm("mov.b64 {%0,%1}, %2;" : "=f"(l1), "=f"(h1) : "l"(a1));
            asm("mov.b64 {%0,%1}, %2;" : "=f"(l2), "=f"(h2) : "l"(a2));
            asm("mov.b64 {%0,%1}, %2;" : "=f"(l3), "=f"(h3) : "l"(a3));
            if_s[tid] = hbase + ((l0 + h0) + (l1 + h1)) + ((l2 + h2) + (l3 + h3));
        }
        __syncthreads();
        if (tid < MD) {
            int hh = tid >> 5;
            int d  = tid & 31;
            int base = hh*65;
            float wv = if_s[base + d];
            float er = 1.f / (1.f + __expf(-if_s[base + 32 + d]));
            float ag = 1.f / (1.f + __expf(-if_s[base + 64]));
            float mo = m_s[tid];
            rv_s[tid] = rv_s[tid] + mo;
            m_s[tid]  = mo * (1.f - er*(1.f/512.f)) + (ag*(1.f/512.f))*wv;
        }
        __syncthreads();
    }
}

// ---------------------------------------------------------------------------
// Launch
// ---------------------------------------------------------------------------
extern "C" void kernel_launch(void* const* d_in, const int* in_sizes, int n_in,
                              void* d_out, int out_size)
{
    const int*   seq   = (const int*)  d_in[0];
    const float* tok   = (const float*)d_in[1];
    const float* pos   = (const float*)d_in[2];
    const float* Wqkv  = (const float*)d_in[3];
    const float* Wo    = (const float*)d_in[4];
    const float* ln1g  = (const float*)d_in[5];
    const float* ln1b  = (const float*)d_in[6];
    const float* ln2g  = (const float*)d_in[7];
    const float* ln2b  = (const float*)d_in[8];
    const float* W1    = (const float*)d_in[9];
    const float* b1    = (const float*)d_in[10];
    const float* W2    = (const float*)d_in[11];
    const float* b2    = (const float*)d_in[12];
    const float* lnfg  = (const float*)d_in[13];
    const float* lnfb  = (const float*)d_in[14];
    const float* Wlog  = (const float*)d_in[15];
    const float* blog  = (const float*)d_in[16];
    const float* Wif   = (const float*)d_in[17];
    const float* bif   = (const float*)d_in[18];
    float* out = (float*)d_out;

    float *gx, *gqkv, *gatt, *gff, *gHif;
    __half *gch, *gwlh;
    cudaGetSymbolAddress((void**)&gx,   g_x);
    cudaGetSymbolAddress((void**)&gqkv, g_qkv);
    cudaGetSymbolAddress((void**)&gatt, g_att);
    cudaGetSymbolAddress((void**)&gff,  g_ff);
    cudaGetSymbolAddress((void**)&gHif, g_Hif);
    cudaGetSymbolAddress((void**)&gch,  g_ch);
    cudaGetSymbolAddress((void**)&gwlh, g_wlh);

    wconv_kernel<<<(CDIM*VOCAB)/1024, 256>>>(Wlog, gwlh);

    embed_kernel<<<BT, DD>>>(seq, tok, pos, gx);

    for (int l = 0; l < 2; l++) {
        tc_gemm<false, true><<<dim3(12, 8), 128>>>(
            3*DD, DD, gx, DD, Wqkv + (long)l*DD*3*DD, 3*DD,
            gqkv, 3*DD, nullptr, nullptr, ln1g + l*DD, ln1b + l*DD);
        attention_kernel<<<dim3(NH, BB, TT/QC), 128>>>(gqkv, gatt);
        tc_gemm_small<<<dim3(8, 16), 128>>>(
            DD, DD, gatt, DD, Wo + (long)l*DD*DD, DD,
            gx, DD, nullptr, gx);
        tc_gemm<true, true><<<dim3(16, 8), 128>>>(
            FF_, DD, gx, DD, W1 + (long)l*DD*FF_, FF_,
            gff, FF_, b1 + l*FF_, nullptr, ln2g + l*DD, ln2b + l*DD);
        tc_gemm_small<<<dim3(8, 16), 128>>>(
            DD, FF_, gff, FF_, W2 + (long)l*FF_*DD, DD,
            gx, DD, b2 + l*DD, gx);
    }

    tc_gemm<false, true><<<dim3((IFACE + 63)/64, 8), 128>>>(
        IFACE, DD, gx, DD, Wif, IFACE, gHif, IFACE, bif, nullptr, lnfg, lnfb);

    lnf_half_kernel<<<BT, DD>>>(gx, lnfg, lnfb, gch);

    scan_kernel<<<BB, 320>>>(gHif, Wif, gch);

    logits_f16_kernel<<<dim3(4, VOCAB/64), 256>>>(gch, gwlh, out, blog);
}

// round 16
// speedup vs baseline: 1.0157x; 1.0157x over previous
#include <cuda_runtime.h>
#include <cuda_bf16.h>
#include <cuda_fp16.h>
#include <math.h>
#include <cstdint>

// ---------------------------------------------------------------------------
// Problem constants
// ---------------------------------------------------------------------------
#define BB 4
#define TT 128
#define DD 256
#define FF_ 1024
#define NH 8
#define HD_ATT 32
#define VOCAB 32000
#define MD 128
#define IFACE 516       // MH*(4*HD+1)
#define CDIM 384        // D + MD
#define BT (BB*TT)      // 512

// logits smem layout constants (halves)
#define LG_STAGES 3
#define LG_ASTRIDE 40
#define LG_BSTRIDE 136
#define LG_ASTAGE (128*LG_ASTRIDE)         // 5120 halves
#define LG_BSTAGE (32*LG_BSTRIDE)          // 4352 halves
#define LG_BOFF   (LG_STAGES*LG_ASTAGE)    // 15360 halves
#define LG_SMEM_BYTES ((LG_STAGES*(LG_ASTAGE + LG_BSTAGE))*2)   // 56832 B

// ---------------------------------------------------------------------------
// Scratch (device globals; no allocation allowed)
// ---------------------------------------------------------------------------
__device__ float g_x  [BT*DD];
__device__ float g_qkv[BT*3*DD];
__device__ float g_att[BT*DD];
__device__ float g_ff [BT*FF_];
__device__ float g_Hif[BT*IFACE];
__device__ __align__(16) __half g_ch[BT*CDIM];      // concat [lnf(x) | rv] fp16
__device__ __align__(16) __half g_wlh[CDIM*VOCAB];  // W_logits pre-converted fp16

// ---------------------------------------------------------------------------
// W_logits fp32 -> fp16 (one-time per launch; no deps, runs first)
// ---------------------------------------------------------------------------
__global__ void wconv_kernel(const float* __restrict__ W, __half* __restrict__ Wh)
{
    long i = ((long)blockIdx.x * 256 + threadIdx.x) * 4;
    float4 v = *reinterpret_cast<const float4*>(W + i);
    __half2 h0 = __floats2half2_rn(v.x, v.y);
    __half2 h1 = __floats2half2_rn(v.z, v.w);
    uint2 u;
    u.x = *reinterpret_cast<unsigned*>(&h0);
    u.y = *reinterpret_cast<unsigned*>(&h1);
    *reinterpret_cast<uint2*>(Wh + i) = u;
}

// ---------------------------------------------------------------------------
// Embedding
// ---------------------------------------------------------------------------
__global__ void embed_kernel(const int* __restrict__ seq,
                             const float* __restrict__ tok,
                             const float* __restrict__ pos,
                             float* __restrict__ x)
{
    int bt = blockIdx.x;
    int d  = threadIdx.x;
    int t  = bt & (TT-1);
    x[bt*DD + d] = tok[(long)seq[bt]*DD + d] + pos[t*DD + d];
}

// ---------------------------------------------------------------------------
// TF32 / cp.async helpers
// ---------------------------------------------------------------------------
__device__ __forceinline__ unsigned f2tf32(float x) {
    unsigned r;
    asm("cvt.rna.tf32.f32 %0, %1;" : "=r"(r) : "f"(x));
    return r;
}
__device__ __forceinline__ void mma_tf32(float* c, const unsigned* a, const unsigned* b) {
    asm volatile(
        "mma.sync.aligned.m16n8k8.row.col.f32.tf32.tf32.f32 "
        "{%0,%1,%2,%3}, {%4,%5,%6,%7}, {%8,%9}, {%0,%1,%2,%3};"
        : "+f"(c[0]), "+f"(c[1]), "+f"(c[2]), "+f"(c[3])
        : "r"(a[0]), "r"(a[1]), "r"(a[2]), "r"(a[3]),
          "r"(b[0]), "r"(b[1]));
}
__device__ __forceinline__ uint32_t smem_u32(const void* p) {
    uint32_t a;
    asm("{ .reg .u64 t; cvta.to.shared.u64 t, %1; cvt.u32.u64 %0, t; }" : "=r"(a) : "l"(p));
    return a;
}
__device__ __forceinline__ void cp_async16(uint32_t saddr, const void* gptr) {
    asm volatile("cp.async.cg.shared.global [%0], [%1], 16;" :: "r"(saddr), "l"(gptr));
}
__device__ __forceinline__ void cp_commit() {
    asm volatile("cp.async.commit_group;" ::: "memory");
}
__device__ __forceinline__ void cp_wait3() {
    asm volatile("cp.async.wait_group 3;" ::: "memory");
}
__device__ __forceinline__ void cp_wait2() {
    asm volatile("cp.async.wait_group 2;" ::: "memory");
}
__device__ __forceinline__ void cp_wait1() {
    asm volatile("cp.async.wait_group 1;" ::: "memory");
}
__device__ __forceinline__ void cp_wait0() {
    asm volatile("cp.async.wait_group 0;" ::: "memory");
}
__device__ __forceinline__ void cp_wait_n(int n) {
    if (n >= 3) cp_wait3();
    else if (n == 2) cp_wait2();
    else if (n == 1) cp_wait1();
    else cp_wait0();
}

// ---------------------------------------------------------------------------
// FP16 mma helpers (logits GEMM)
// ---------------------------------------------------------------------------
__device__ __forceinline__ void ldsm_x4(unsigned* r, uint32_t addr) {
    asm volatile("ldmatrix.sync.aligned.m8n8.x4.shared.b16 {%0,%1,%2,%3}, [%4];"
        : "=r"(r[0]), "=r"(r[1]), "=r"(r[2]), "=r"(r[3]) : "r"(addr));
}
__device__ __forceinline__ void ldsm_x4_t(unsigned* r, uint32_t addr) {
    asm volatile("ldmatrix.sync.aligned.m8n8.x4.trans.shared.b16 {%0,%1,%2,%3}, [%4];"
        : "=r"(r[0]), "=r"(r[1]), "=r"(r[2]), "=r"(r[3]) : "r"(addr));
}
__device__ __forceinline__ void mma_f16(float* c, const unsigned* a, unsigned b0, unsigned b1) {
    asm volatile(
        "mma.sync.aligned.m16n8k16.row.col.f32.f16.f16.f32 "
        "{%0,%1,%2,%3}, {%4,%5,%6,%7}, {%8,%9}, {%0,%1,%2,%3};"
        : "+f"(c[0]), "+f"(c[1]), "+f"(c[2]), "+f"(c[3])
        : "r"(a[0]), "r"(a[1]), "r"(a[2]), "r"(a[3]),
          "r"(b0), "r"(b1));
}

// ---------------------------------------------------------------------------
// FP16 logits GEMM: 128x128 block tile, 3-stage cp.async (dynamic smem),
// 8 warps (2m x 4n), warp tile 64x32, mma m16n8k16.
// Grid (4, 250), m fastest: 4 m-blocks share each B n-strip (L2 hit).
// A stride 40 halves (80 B), B stride 136 halves (272 B) — both 16B-divisible.
// ---------------------------------------------------------------------------
__global__ __launch_bounds__(256, 2) void logits_f16_kernel(
    const __half* __restrict__ A,
    const __half* __restrict__ Bh_g,
    float* __restrict__ C,
    const float* __restrict__ bias)
{
    extern __shared__ __half lsm[];
    const uint32_t ahBase = smem_u32(lsm);
    const uint32_t bhBase = ahBase + LG_BOFF*2;

    const int tid  = threadIdx.x;
    const int lane = tid & 31;
    const int wid  = tid >> 5;
    const int wm   = (wid >> 2) * 64;
    const int wn   = (wid & 3) * 32;
    const int m0   = blockIdx.x * 128;
    const int n0   = blockIdx.y * 128;

    // A tile: 128 rows x 32 halves = 512 x 16B chunks; 2 per thread
    // B tile: 32 rows x 128 halves = 512 x 16B chunks; 2 per thread
    auto fill = [&](int s, int k0) {
        #pragma unroll
        for (int i = 0; i < 2; i++) {
            int id = i*256 + tid;
            int r  = id >> 2;
            int c  = (id & 3) << 3;
            cp_async16(ahBase + (uint32_t)((s*LG_ASTAGE + r*LG_ASTRIDE + c) << 1),
                       A + (long)(m0 + r)*CDIM + k0 + c);
        }
        #pragma unroll
        for (int i = 0; i < 2; i++) {
            int id = i*256 + tid;
            int r  = id >> 4;
            int c  = (id & 15) << 3;
            cp_async16(bhBase + (uint32_t)((s*LG_BSTAGE + r*LG_BSTRIDE + c) << 1),
                       Bh_g + (long)(k0 + r)*VOCAB + n0 + c);
        }
        cp_commit();
    };

    float acc[16][4];
    #pragma unroll
    for (int i = 0; i < 16; i++)
        #pragma unroll
        for (int j = 0; j < 4; j++) acc[i][j] = 0.f;

    fill(0, 0);
    fill(1, 32);

    const int nt = CDIM/32;   // 12
    #pragma unroll 1
    for (int kt = 0; kt < nt; kt++) {
        if (kt + 2 < nt) fill((kt + 2) % 3, (kt + 2) * 32);
        int ahead = nt - 1 - kt;
        cp_wait_n(ahead < 2 ? ahead : 2);
        __syncthreads();

        const int buf = kt % 3;
        const uint32_t aBuf = ahBase + (uint32_t)((buf*LG_ASTAGE) << 1);
        const uint32_t bBuf = bhBase + (uint32_t)((buf*LG_BSTAGE) << 1);

        #pragma unroll
        for (int ks = 0; ks < 32; ks += 16) {
            unsigned af[4][4], bf[2][4];
            #pragma unroll
            for (int mt = 0; mt < 4; mt++) {
                int row = wm + mt*16 + (lane & 15);
                int col = ks + ((lane & 16) >> 1);
                ldsm_x4(af[mt], aBuf + (uint32_t)((row*LG_ASTRIDE + col) << 1));
            }
            #pragma unroll
            for (int pr = 0; pr < 2; pr++) {
                int row = ks + (lane & 15);
                int col = wn + pr*16 + ((lane & 16) >> 1);
                ldsm_x4_t(bf[pr], bBuf + (uint32_t)((row*LG_BSTRIDE + col) << 1));
            }
            #pragma unroll
            for (int mt = 0; mt < 4; mt++)
                #pragma unroll
                for (int nt2 = 0; nt2 < 4; nt2++)
                    mma_f16(acc[mt*4 + nt2], af[mt],
                            bf[nt2 >> 1][(nt2 & 1)*2], bf[nt2 >> 1][(nt2 & 1)*2 + 1]);
        }
        __syncthreads();
    }

    const int g  = lane >> 2;
    const int tg = lane & 3;
    #pragma unroll
    for (int nt2 = 0; nt2 < 4; nt2++) {
        int n = n0 + wn + nt2*8 + 2*tg;
        float2 bz = *reinterpret_cast<const float2*>(bias + n);
        #pragma unroll
        for (int mt = 0; mt < 4; mt++) {
            int m = m0 + wm + mt*16 + g;
            float* c = acc[mt*4 + nt2];
            *reinterpret_cast<float2*>(C + (long)m*VOCAB + n)     = make_float2(c[0]+bz.x, c[1]+bz.y);
            *reinterpret_cast<float2*>(C + (long)(m+8)*VOCAB + n) = make_float2(c[2]+bz.x, c[3]+bz.y);
        }
    }
}

// ---------------------------------------------------------------------------
// TF32 small GEMM, 2-stage cp.async, optional fused LayerNorm on A.
// When LN and chout != nullptr: blocks with blockIdx.x == 0 also write the
// normalized A rows as fp16 into chout (stride CDIM) — fuses lnf_half.
// ---------------------------------------------------------------------------
template<bool GELU, bool LN>
__global__ __launch_bounds__(128) void tc_gemm(
    int N, int K,
    const float* __restrict__ A, int lda,
    const float* __restrict__ B, int ldb,
    float* __restrict__ C, int ldc,
    const float* __restrict__ bias,
    const float* __restrict__ residual,
    const float* __restrict__ ln_g,
    const float* __restrict__ ln_b,
    __half* __restrict__ chout)
{
    __shared__ float As[2][64][36];
    __shared__ float Bs[2][32][68];
    __shared__ float smean[64];
    __shared__ float srstd[64];
    __shared__ float sg[256];
    __shared__ float sb[256];

    const int tid  = threadIdx.x;
    const int lane = tid & 31;
    const int wid  = tid >> 5;
    const int wm   = (wid >> 1) * 32;
    const int wn   = (wid & 1) * 32;
    const int m0   = blockIdx.y * 64;
    const int n0   = blockIdx.x * 64;
    const int g    = lane >> 2;
    const int tg   = lane & 3;
    const int nt   = K >> 5;

    const uint32_t asBase = smem_u32(&As[0][0][0]);
    const uint32_t bsBase = smem_u32(&Bs[0][0][0]);

    const int a_r  = tid >> 3;
    const int a_c4 = (tid & 7) << 2;
    const int b_r  = tid >> 4;
    const int b_c4 = (tid & 15) << 2;

    auto fill = [&](int s, int k0) {
        #pragma unroll
        for (int i = 0; i < 4; i++) {
            int r = a_r + i*16;
            cp_async16(asBase + (uint32_t)(((s*64 + r)*36 + a_c4) << 2),
                       A + (long)(m0 + r)*lda + k0 + a_c4);
        }
        #pragma unroll
        for (int i = 0; i < 4; i++) {
            int r = b_r + i*8;
            if (n0 + b_c4 < N) {
                cp_async16(bsBase + (uint32_t)(((s*32 + r)*68 + b_c4) << 2),
                           B + (long)(k0 + r)*ldb + n0 + b_c4);
            } else {
                *reinterpret_cast<float4*>(&Bs[s][r][b_c4]) = make_float4(0.f,0.f,0.f,0.f);
            }
        }
        cp_commit();
    };

    fill(0, 0);

    if (LN) {
        int r  = tid >> 1;
        int hf = tid & 1;
        const float* rowp = A + (long)(m0 + r)*lda;
        float s = 0.f, s2 = 0.f;
        for (int i = hf*4; i < K; i += 8) {
            float4 u = *reinterpret_cast<const float4*>(rowp + i);
            s  += u.x + u.y + u.z + u.w;
            s2 += u.x*u.x + u.y*u.y + u.z*u.z + u.w*u.w;
        }
        s  += __shfl_xor_sync(0xffffffffu, s, 1);
        s2 += __shfl_xor_sync(0xffffffffu, s2, 1);
        if (!hf) {
            float inv = 1.f / (float)K;
            float mu  = s * inv;
            float var = s2 * inv - mu*mu;
            smean[r] = mu;
            srstd[r] = rsqrtf(var + 1e-5f);
        }
        if (tid < 64) {
            *reinterpret_cast<float4*>(&sg[tid*4]) = *reinterpret_cast<const float4*>(ln_g + tid*4);
        } else {
            int t = tid - 64;
            *reinterpret_cast<float4*>(&sb[t*4]) = *reinterpret_cast<const float4*>(ln_b + t*4);
        }
        __syncthreads();

        // Fused lnf -> fp16 concat (only the n0==0 blocks; rows m0..m0+63)
        if (chout && blockIdx.x == 0) {
            for (int idx = tid; idx < 64*64; idx += 128) {
                int r2 = idx >> 6;
                int c4 = (idx & 63) << 2;
                float4 u = *reinterpret_cast<const float4*>(A + (long)(m0 + r2)*lda + c4);
                float mu = smean[r2], rs = srstd[r2];
                float4 gm = *reinterpret_cast<const float4*>(&sg[c4]);
                float4 bt = *reinterpret_cast<const float4*>(&sb[c4]);
                __half2 h0 = __floats2half2_rn((u.x - mu)*rs*gm.x + bt.x,
                                               (u.y - mu)*rs*gm.y + bt.y);
                __half2 h1 = __floats2half2_rn((u.z - mu)*rs*gm.z + bt.z,
                                               (u.w - mu)*rs*gm.w + bt.w);
                uint2 o;
                o.x = *reinterpret_cast<unsigned*>(&h0);
                o.y = *reinterpret_cast<unsigned*>(&h1);
                *reinterpret_cast<uint2*>(chout + (long)(m0 + r2)*CDIM + c4) = o;
            }
        }
    }

    float rs_[4], mrs_[4];
    if (LN) {
        #pragma unroll
        for (int q = 0; q < 4; q++) {
            int r = wm + q*8 + g;
            rs_[q]  = srstd[r];
            mrs_[q] = smean[r] * rs_[q];
        }
    }

    float acc[8][4];
    #pragma unroll
    for (int i = 0; i < 8; i++)
        #pragma unroll
        for (int j = 0; j < 4; j++) acc[i][j] = 0.f;

    #pragma unroll 1
    for (int kt = 0; kt < nt; kt++) {
        const bool more = (kt + 1) < nt;
        if (more) fill((kt + 1) & 1, (kt + 1) * 32);
        if (more) cp_wait1(); else cp_wait0();
        __syncthreads();

        const int buf = kt & 1;
        const int k0  = kt * 32;

        #pragma unroll
        for (int ks = 0; ks < 32; ks += 8) {
            unsigned af[2][4], bf[4][2];
            float gm0 = 0.f, gm4 = 0.f, bt0 = 0.f, bt4 = 0.f;
            if (LN) {
                gm0 = sg[k0 + ks + tg];   gm4 = sg[k0 + ks + tg + 4];
                bt0 = sb[k0 + ks + tg];   bt4 = sb[k0 + ks + tg + 4];
            }
            #pragma unroll
            for (int mt = 0; mt < 2; mt++) {
                int mr = wm + mt*16 + g;
                float r00 = As[buf][mr  ][ks + tg    ];
                float r10 = As[buf][mr+8][ks + tg    ];
                float r04 = As[buf][mr  ][ks + tg + 4];
                float r14 = As[buf][mr+8][ks + tg + 4];
                if (LN) {
                    float rsa = rs_[mt*2],   ma = mrs_[mt*2];
                    float rsb = rs_[mt*2+1], mb = mrs_[mt*2+1];
                    r00 = fmaf(fmaf(r00, rsa, -ma), gm0, bt0);
                    r10 = fmaf(fmaf(r10, rsb, -mb), gm0, bt0);
                    r04 = fmaf(fmaf(r04, rsa, -ma), gm4, bt4);
                    r14 = fmaf(fmaf(r14, rsb, -mb), gm4, bt4);
                }
                af[mt][0] = f2tf32(r00);
                af[mt][1] = f2tf32(r10);
                af[mt][2] = f2tf32(r04);
                af[mt][3] = f2tf32(r14);
            }
            #pragma unroll
            for (int nt2 = 0; nt2 < 4; nt2++) {
                int nc = wn + nt2*8 + g;
                bf[nt2][0] = f2tf32(Bs[buf][ks + tg    ][nc]);
                bf[nt2][1] = f2tf32(Bs[buf][ks + tg + 4][nc]);
            }
            #pragma unroll
            for (int mt = 0; mt < 2; mt++)
                #pragma unroll
                for (int nt2 = 0; nt2 < 4; nt2++)
                    mma_tf32(acc[mt*4 + nt2], af[mt], bf[nt2]);
        }
        __syncthreads();
    }

    #pragma unroll
    for (int nt2 = 0; nt2 < 4; nt2++) {
        int n = n0 + wn + nt2*8 + 2*tg;
        if (n < N) {
            float2 bz = make_float2(0.f, 0.f);
            if (bias) bz = *reinterpret_cast<const float2*>(bias + n);
            #pragma unroll
            for (int mt = 0; mt < 2; mt++) {
                int m = m0 + wm + mt*16 + g;
                float* c = acc[mt*4 + nt2];
                float v[4] = {c[0]+bz.x, c[1]+bz.y, c[2]+bz.x, c[3]+bz.y};
                if (GELU) {
                    #pragma unroll
                    for (int q = 0; q < 4; q++) {
                        float u = v[q];
                        float tt = 0.7978845608028654f * (u + 0.044715f*u*u*u);
                        v[q] = 0.5f*u*(1.f + tanhf(tt));
                    }
                }
                if (residual) {
                    float2 r0 = *reinterpret_cast<const float2*>(residual + (long)m*ldc + n);
                    float2 r1 = *reinterpret_cast<const float2*>(residual + (long)(m+8)*ldc + n);
                    v[0] += r0.x; v[1] += r0.y; v[2] += r1.x; v[3] += r1.y;
                }
                *reinterpret_cast<float2*>(C + (long)m*ldc + n)     = make_float2(v[0], v[1]);
                *reinterpret_cast<float2*>(C + (long)(m+8)*ldc + n) = make_float2(v[2], v[3]);
            }
        }
    }
}

// ---------------------------------------------------------------------------
// TF32 tiny-tile GEMM (Wo, FF2): 32x32 tile, BK=32, 4-stage cp.async.
// ---------------------------------------------------------------------------
__global__ __launch_bounds__(128) void tc_gemm_small(
    int N, int K,
    const float* __restrict__ A, int lda,
    const float* __restrict__ B, int ldb,
    float* __restrict__ C, int ldc,
    const float* __restrict__ bias,
    const float* __restrict__ residual)
{
    __shared__ float As[4][32][36];
    __shared__ float Bs[4][32][36];

    const int tid  = threadIdx.x;
    const int lane = tid & 31;
    const int wid  = tid >> 5;
    const int wm   = (wid >> 1) * 16;
    const int wn   = (wid & 1) * 16;
    const int m0   = blockIdx.y * 32;
    const int n0   = blockIdx.x * 32;
    const int g    = lane >> 2;
    const int tg   = lane & 3;
    const int nt   = K >> 5;

    const uint32_t asBase = smem_u32(&As[0][0][0]);
    const uint32_t bsBase = smem_u32(&Bs[0][0][0]);
    const int r_  = tid >> 3;
    const int c4  = (tid & 7) << 2;

    auto fill = [&](int s, int k0) {
        #pragma unroll
        for (int i = 0; i < 2; i++) {
            int r = r_ + i*16;
            cp_async16(asBase + (uint32_t)(((s*32 + r)*36 + c4) << 2),
                       A + (long)(m0 + r)*lda + k0 + c4);
            cp_async16(bsBase + (uint32_t)(((s*32 + r)*36 + c4) << 2),
                       B + (long)(k0 + r)*ldb + n0 + c4);
        }
        cp_commit();
    };

    const int pre = (nt < 3) ? nt : 3;
    for (int s = 0; s < pre; s++) fill(s, s*32);

    float acc[2][4];
    #pragma unroll
    for (int i = 0; i < 2; i++)
        #pragma unroll
        for (int j = 0; j < 4; j++) acc[i][j] = 0.f;

    #pragma unroll 1
    for (int kt = 0; kt < nt; kt++) {
        if (kt + 3 < nt) fill((kt + 3) & 3, (kt + 3) * 32);
        int ahead = nt - 1 - kt;
        cp_wait_n(ahead < 3 ? ahead : 3);
        __syncthreads();

        const int buf = kt & 3;
        #pragma unroll
        for (int ks = 0; ks < 32; ks += 8) {
            unsigned af[4], bf[2][2];
            af[0] = f2tf32(As[buf][wm + g    ][ks + tg    ]);
            af[1] = f2tf32(As[buf][wm + g + 8][ks + tg    ]);
            af[2] = f2tf32(As[buf][wm + g    ][ks + tg + 4]);
            af[3] = f2tf32(As[buf][wm + g + 8][ks + tg + 4]);
            #pragma unroll
            for (int nt2 = 0; nt2 < 2; nt2++) {
                int nc = wn + nt2*8 + g;
                bf[nt2][0] = f2tf32(Bs[buf][ks + tg    ][nc]);
                bf[nt2][1] = f2tf32(Bs[buf][ks + tg + 4][nc]);
            }
            #pragma unroll
            for (int nt2 = 0; nt2 < 2; nt2++)
                mma_tf32(acc[nt2], af, bf[nt2]);
        }
        __syncthreads();
    }

    #pragma unroll
    for (int nt2 = 0; nt2 < 2; nt2++) {
        int n = n0 + wn + nt2*8 + 2*tg;
        float2 bz = make_float2(0.f, 0.f);
        if (bias) bz = *reinterpret_cast<const float2*>(bias + n);
        int m = m0 + wm + g;
        float* c = acc[nt2];
        float v[4] = {c[0]+bz.x, c[1]+bz.y, c[2]+bz.x, c[3]+bz.y};
        if (residual) {
            float2 r0 = *reinterpret_cast<const float2*>(residual + (long)m*ldc + n);
            float2 r1 = *reinterpret_cast<const float2*>(residual + (long)(m+8)*ldc + n);
            v[0] += r0.x; v[1] += r0.y; v[2] += r1.x; v[3] += r1.y;
        }
        *reinterpret_cast<float2*>(C + (long)m*ldc + n)     = make_float2(v[0], v[1]);
        *reinterpret_cast<float2*>(C + (long)(m+8)*ldc + n) = make_float2(v[2], v[3]);
    }
}

// ---------------------------------------------------------------------------
// Causal attention: block = (head, batch, q-chunk of 8). 512 blocks.
// ---------------------------------------------------------------------------
#define QC 8
__global__ __launch_bounds__(128) void attention_kernel(
    const float* __restrict__ qkv, float* __restrict__ att_out)
{
    __shared__ float Ks[TT][36];
    __shared__ float Vs[TT][32];
    __shared__ __align__(16) float Ps[QC][132];
    const int h  = blockIdx.x;
    const int b  = blockIdx.y;
    const int qc = blockIdx.z;
    const int tid = threadIdx.x;
    const float scale = 0.17677669529663687f;

    {
        const float* kp = qkv + (long)(b*TT + tid)*(3*DD) + DD + h*HD_ATT;
        const float* vp = kp + DD;
        #pragma unroll
        for (int d = 0; d < 32; d += 4) {
            *reinterpret_cast<float4*>(&Ks[tid][d]) = *reinterpret_cast<const float4*>(kp + d);
            *reinterpret_cast<float4*>(&Vs[tid][d]) = *reinterpret_cast<const float4*>(vp + d);
        }
    }
    __syncthreads();

    const int q = tid >> 4;
    const int j = tid & 15;
    const int qglob = qc*QC + q;

    float qv[32];
    {
        const float* qp = qkv + (long)(b*TT + qglob)*(3*DD) + h*HD_ATT;
        #pragma unroll
        for (int d = 0; d < 32; d += 4) {
            float4 t = *reinterpret_cast<const float4*>(qp + d);
            qv[d]=t.x; qv[d+1]=t.y; qv[d+2]=t.z; qv[d+3]=t.w;
        }
    }

    float s[8];
    float mmax = -1e30f;
    #pragma unroll
    for (int kk = 0; kk < 8; kk++) {
        int k = kk*16 + j;
        float acc = 0.f;
        #pragma unroll
        for (int d = 0; d < 32; d += 4) {
            float4 kv = *reinterpret_cast<const float4*>(&Ks[k][d]);
            acc += qv[d]*kv.x + qv[d+1]*kv.y + qv[d+2]*kv.z + qv[d+3]*kv.w;
        }
        s[kk] = (k <= qglob) ? acc*scale : -1e30f;
        mmax = fmaxf(mmax, s[kk]);
    }
    #pragma unroll
    for (int o = 1; o < 16; o <<= 1)
        mmax = fmaxf(mmax, __shfl_xor_sync(0xffffffffu, mmax, o));

    float l = 0.f;
    #pragma unroll
    for (int kk = 0; kk < 8; kk++) {
        float p = __expf(s[kk] - mmax);
        l += p;
        Ps[q][kk*16 + j] = p;
    }
    #pragma unroll
    for (int o = 1; o < 16; o <<= 1)
        l += __shfl_xor_sync(0xffffffffu, l, o);
    float linv = 1.f / l;
    __syncthreads();

    float ox = 0.f, oy = 0.f;
    #pragma unroll 4
    for (int k = 0; k < TT; k += 4) {
        float4 p4 = *reinterpret_cast<const float4*>(&Ps[q][k]);
        float2 v0 = *reinterpret_cast<const float2*>(&Vs[k  ][j*2]);
        float2 v1 = *reinterpret_cast<const float2*>(&Vs[k+1][j*2]);
        float2 v2 = *reinterpret_cast<const float2*>(&Vs[k+2][j*2]);
        float2 v3 = *reinterpret_cast<const float2*>(&Vs[k+3][j*2]);
        ox += p4.x*v0.x + p4.y*v1.x + p4.z*v2.x + p4.w*v3.x;
        oy += p4.x*v0.y + p4.y*v1.y + p4.z*v2.y + p4.w*v3.y;
    }
    float2 o2 = make_float2(ox*linv, oy*linv);
    *reinterpret_cast<float2*>(att_out + (long)(b*TT + qglob)*DD + h*HD_ATT + j*2) = o2;
}

// ---------------------------------------------------------------------------
// Memory scan (collapsed; see derivation R2).  fma.rn.f32x2 GEMV, 4 accs.
// ---------------------------------------------------------------------------
__global__ __launch_bounds__(320) void scan_kernel(
    const float* __restrict__ Hif,
    const float* __restrict__ W_iface,
    __half* __restrict__ ch)
{
    int b   = blockIdx.x;
    int tid = threadIdx.x;
    __shared__ __align__(16) float rv_s[MD];
    __shared__ float m_s[MD];
    __shared__ float if_s[260];

    unsigned long long w2[64];
    int gcol = 0;
    if (tid < 260) {
        gcol = (tid/65)*129 + 64 + (tid%65);
        #pragma unroll
        for (int k = 0; k < 64; k++) {
            float lo = W_iface[(long)(256 + 2*k    )*IFACE + gcol];
            float hi = W_iface[(long)(256 + 2*k + 1)*IFACE + gcol];
            asm("mov.b64 %0, {%1,%2};" : "=l"(w2[k]) : "f"(lo), "f"(hi));
        }
    }
    if (tid < MD) { rv_s[tid] = 0.f; m_s[tid] = 0.f; }
    __syncthreads();

    const unsigned long long* rv2 = reinterpret_cast<const unsigned long long*>(rv_s);

    for (int t = 0; t < TT; t++) {
        if (tid < MD)
            ch[(long)(b*TT + t)*CDIM + DD + tid] = __float2half(rv_s[tid]);
        if (tid < 260) {
            float hbase = Hif[(long)(b*TT + t)*IFACE + gcol];
            unsigned long long a0 = 0ull, a1 = 0ull, a2 = 0ull, a3 = 0ull;
            #pragma unroll
            for (int k = 0; k < 64; k += 4) {
                asm("fma.rn.f32x2 %0, %1, %2, %0;" : "+l"(a0) : "l"(rv2[k  ]), "l"(w2[k  ]));
                asm("fma.rn.f32x2 %0, %1, %2, %0;" : "+l"(a1) : "l"(rv2[k+1]), "l"(w2[k+1]));
                asm("fma.rn.f32x2 %0, %1, %2, %0;" : "+l"(a2) : "l"(rv2[k+2]), "l"(w2[k+2]));
                asm("fma.rn.f32x2 %0, %1, %2, %0;" : "+l"(a3) : "l"(rv2[k+3]), "l"(w2[k+3]));
            }
            float l0, h0, l1, h1, l2, h2, l3, h3;
            asm("mov.b64 {%0,%1}, %2;" : "=f"(l0), "=f"(h0) : "l"(a0));
            asm("mov.b64 {%0,%1}, %2;" : "=f"(l1), "=f"(h1) : "l"(a1));
            asm("mov.b64 {%0,%1}, %2;" : "=f"(l2), "=f"(h2) : "l"(a2));
            asm("mov.b64 {%0,%1}, %2;" : "=f"(l3), "=f"(h3) : "l"(a3));
            if_s[tid] = hbase + ((l0 + h0) + (l1 + h1)) + ((l2 + h2) + (l3 + h3));
        }
        __syncthreads();
        if (tid < MD) {
            int hh = tid >> 5;
            int d  = tid & 31;
            int base = hh*65;
            float wv = if_s[base + d];
            float er = 1.f / (1.f + __expf(-if_s[base + 32 + d]));
            float ag = 1.f / (1.f + __expf(-if_s[base + 64]));
            float mo = m_s[tid];
            rv_s[tid] = rv_s[tid] + mo;
            m_s[tid]  = mo * (1.f - er*(1.f/512.f)) + (ag*(1.f/512.f))*wv;
        }
        __syncthreads();
    }
}

// ---------------------------------------------------------------------------
// Launch
// ---------------------------------------------------------------------------
extern "C" void kernel_launch(void* const* d_in, const int* in_sizes, int n_in,
                              void* d_out, int out_size)
{
    const int*   seq   = (const int*)  d_in[0];
    const float* tok   = (const float*)d_in[1];
    const float* pos   = (const float*)d_in[2];
    const float* Wqkv  = (const float*)d_in[3];
    const float* Wo    = (const float*)d_in[4];
    const float* ln1g  = (const float*)d_in[5];
    const float* ln1b  = (const float*)d_in[6];
    const float* ln2g  = (const float*)d_in[7];
    const float* ln2b  = (const float*)d_in[8];
    const float* W1    = (const float*)d_in[9];
    const float* b1    = (const float*)d_in[10];
    const float* W2    = (const float*)d_in[11];
    const float* b2    = (const float*)d_in[12];
    const float* lnfg  = (const float*)d_in[13];
    const float* lnfb  = (const float*)d_in[14];
    const float* Wlog  = (const float*)d_in[15];
    const float* blog  = (const float*)d_in[16];
    const float* Wif   = (const float*)d_in[17];
    const float* bif   = (const float*)d_in[18];
    float* out = (float*)d_out;

    float *gx, *gqkv, *gatt, *gff, *gHif;
    __half *gch, *gwlh;
    cudaGetSymbolAddress((void**)&gx,   g_x);
    cudaGetSymbolAddress((void**)&gqkv, g_qkv);
    cudaGetSymbolAddress((void**)&gatt, g_att);
    cudaGetSymbolAddress((void**)&gff,  g_ff);
    cudaGetSymbolAddress((void**)&gHif, g_Hif);
    cudaGetSymbolAddress((void**)&gch,  g_ch);
    cudaGetSymbolAddress((void**)&gwlh, g_wlh);

    static bool attr_set = false;
    if (!attr_set) {
        cudaFuncSetAttribute(logits_f16_kernel,
                             cudaFuncAttributeMaxDynamicSharedMemorySize,
                             LG_SMEM_BYTES);
        attr_set = true;
    }

    wconv_kernel<<<(CDIM*VOCAB)/1024, 256>>>(Wlog, gwlh);

    embed_kernel<<<BT, DD>>>(seq, tok, pos, gx);

    for (int l = 0; l < 2; l++) {
        tc_gemm<false, true><<<dim3(12, 8), 128>>>(
            3*DD, DD, gx, DD, Wqkv + (long)l*DD*3*DD, 3*DD,
            gqkv, 3*DD, nullptr, nullptr, ln1g + l*DD, ln1b + l*DD, nullptr);
        attention_kernel<<<dim3(NH, BB, TT/QC), 128>>>(gqkv, gatt);
        tc_gemm_small<<<dim3(8, 16), 128>>>(
            DD, DD, gatt, DD, Wo + (long)l*DD*DD, DD,
            gx, DD, nullptr, gx);
        tc_gemm<true, true><<<dim3(16, 8), 128>>>(
            FF_, DD, gx, DD, W1 + (long)l*DD*FF_, FF_,
            gff, FF_, b1 + l*FF_, nullptr, ln2g + l*DD, ln2b + l*DD, nullptr);
        tc_gemm_small<<<dim3(8, 16), 128>>>(
            DD, FF_, gff, FF_, W2 + (long)l*FF_*DD, DD,
            gx, DD, b2 + l*DD, gx);
    }

    // interface projection with fused final LN; n0==0 blocks also emit
    // the fp16 concat left half (replaces the lnf_half kernel)
    tc_gemm<false, true><<<dim3((IFACE + 63)/64, 8), 128>>>(
        IFACE, DD, gx, DD, Wif, IFACE, gHif, IFACE, bif, nullptr,
        lnfg, lnfb, gch);

    scan_kernel<<<BB, 320>>>(gHif, Wif, gch);

    logits_f16_kernel<<<dim3(4, VOCAB/128), 256, LG_SMEM_BYTES>>>(gch, gwlh, out, blog);
}

// round 17
// speedup vs baseline: 1.0250x; 1.0092x over previous
#include <cuda_runtime.h>
#include <cuda_bf16.h>
#include <cuda_fp16.h>
#include <math.h>
#include <cstdint>

// ---------------------------------------------------------------------------
// Problem constants
// ---------------------------------------------------------------------------
#define BB 4
#define TT 128
#define DD 256
#define FF_ 1024
#define NH 8
#define HD_ATT 32
#define VOCAB 32000
#define MD 128
#define IFACE 516       // MH*(4*HD+1)
#define CDIM 384        // D + MD
#define BT (BB*TT)      // 512

// logits smem layout constants (halves)
#define LG_STAGES 3
#define LG_ASTRIDE 40
#define LG_BSTRIDE 136
#define LG_ASTAGE (128*LG_ASTRIDE)
#define LG_BSTAGE (32*LG_BSTRIDE)
#define LG_BOFF   (LG_STAGES*LG_ASTAGE)
#define LG_SMEM_BYTES ((LG_STAGES*(LG_ASTAGE + LG_BSTAGE))*2)   // 56832 B

// ---------------------------------------------------------------------------
// Scratch (device globals; no allocation allowed)
// ---------------------------------------------------------------------------
__device__ float g_x  [BT*DD];
__device__ float g_qkv[BT*3*DD];
__device__ float g_att[BT*DD];
__device__ float g_ff [BT*FF_];
__device__ float g_Hif[BT*IFACE];
__device__ __align__(16) __half g_ch[BT*CDIM];      // concat [lnf(x) | rv] fp16
__device__ __align__(16) __half g_wlh[CDIM*VOCAB];  // W_logits pre-converted fp16

// ---------------------------------------------------------------------------
// W_logits fp32 -> fp16 (independent; runs on a side stream)
// ---------------------------------------------------------------------------
__global__ void wconv_kernel(const float* __restrict__ W, __half* __restrict__ Wh)
{
    long i = ((long)blockIdx.x * 256 + threadIdx.x) * 4;
    float4 v = *reinterpret_cast<const float4*>(W + i);
    __half2 h0 = __floats2half2_rn(v.x, v.y);
    __half2 h1 = __floats2half2_rn(v.z, v.w);
    uint2 u;
    u.x = *reinterpret_cast<unsigned*>(&h0);
    u.y = *reinterpret_cast<unsigned*>(&h1);
    *reinterpret_cast<uint2*>(Wh + i) = u;
}

// ---------------------------------------------------------------------------
// Embedding
// ---------------------------------------------------------------------------
__global__ void embed_kernel(const int* __restrict__ seq,
                             const float* __restrict__ tok,
                             const float* __restrict__ pos,
                             float* __restrict__ x)
{
    int bt = blockIdx.x;
    int d  = threadIdx.x;
    int t  = bt & (TT-1);
    x[bt*DD + d] = tok[(long)seq[bt]*DD + d] + pos[t*DD + d];
}

// ---------------------------------------------------------------------------
// TF32 / cp.async helpers
// ---------------------------------------------------------------------------
__device__ __forceinline__ unsigned f2tf32(float x) {
    unsigned r;
    asm("cvt.rna.tf32.f32 %0, %1;" : "=r"(r) : "f"(x));
    return r;
}
__device__ __forceinline__ void mma_tf32(float* c, const unsigned* a, const unsigned* b) {
    asm volatile(
        "mma.sync.aligned.m16n8k8.row.col.f32.tf32.tf32.f32 "
        "{%0,%1,%2,%3}, {%4,%5,%6,%7}, {%8,%9}, {%0,%1,%2,%3};"
        : "+f"(c[0]), "+f"(c[1]), "+f"(c[2]), "+f"(c[3])
        : "r"(a[0]), "r"(a[1]), "r"(a[2]), "r"(a[3]),
          "r"(b[0]), "r"(b[1]));
}
__device__ __forceinline__ uint32_t smem_u32(const void* p) {
    uint32_t a;
    asm("{ .reg .u64 t; cvta.to.shared.u64 t, %1; cvt.u32.u64 %0, t; }" : "=r"(a) : "l"(p));
    return a;
}
__device__ __forceinline__ void cp_async16(uint32_t saddr, const void* gptr) {
    asm volatile("cp.async.cg.shared.global [%0], [%1], 16;" :: "r"(saddr), "l"(gptr));
}
__device__ __forceinline__ void cp_commit() {
    asm volatile("cp.async.commit_group;" ::: "memory");
}
__device__ __forceinline__ void cp_wait3() {
    asm volatile("cp.async.wait_group 3;" ::: "memory");
}
__device__ __forceinline__ void cp_wait2() {
    asm volatile("cp.async.wait_group 2;" ::: "memory");
}
__device__ __forceinline__ void cp_wait1() {
    asm volatile("cp.async.wait_group 1;" ::: "memory");
}
__device__ __forceinline__ void cp_wait0() {
    asm volatile("cp.async.wait_group 0;" ::: "memory");
}
__device__ __forceinline__ void cp_wait_n(int n) {
    if (n >= 3) cp_wait3();
    else if (n == 2) cp_wait2();
    else if (n == 1) cp_wait1();
    else cp_wait0();
}

// ---------------------------------------------------------------------------
// FP16 mma helpers (logits GEMM)
// ---------------------------------------------------------------------------
__device__ __forceinline__ void ldsm_x4(unsigned* r, uint32_t addr) {
    asm volatile("ldmatrix.sync.aligned.m8n8.x4.shared.b16 {%0,%1,%2,%3}, [%4];"
        : "=r"(r[0]), "=r"(r[1]), "=r"(r[2]), "=r"(r[3]) : "r"(addr));
}
__device__ __forceinline__ void ldsm_x4_t(unsigned* r, uint32_t addr) {
    asm volatile("ldmatrix.sync.aligned.m8n8.x4.trans.shared.b16 {%0,%1,%2,%3}, [%4];"
        : "=r"(r[0]), "=r"(r[1]), "=r"(r[2]), "=r"(r[3]) : "r"(addr));
}
__device__ __forceinline__ void mma_f16(float* c, const unsigned* a, unsigned b0, unsigned b1) {
    asm volatile(
        "mma.sync.aligned.m16n8k16.row.col.f32.f16.f16.f32 "
        "{%0,%1,%2,%3}, {%4,%5,%6,%7}, {%8,%9}, {%0,%1,%2,%3};"
        : "+f"(c[0]), "+f"(c[1]), "+f"(c[2]), "+f"(c[3])
        : "r"(a[0]), "r"(a[1]), "r"(a[2]), "r"(a[3]),
          "r"(b0), "r"(b1));
}

// ---------------------------------------------------------------------------
// FP16 logits GEMM: 128x128 block tile, 3-stage cp.async (dynamic smem),
// 8 warps (2m x 4n), warp tile 64x32, mma m16n8k16.  Grid (4, 250), m fastest.
// ---------------------------------------------------------------------------
__global__ __launch_bounds__(256, 2) void logits_f16_kernel(
    const __half* __restrict__ A,
    const __half* __restrict__ Bh_g,
    float* __restrict__ C,
    const float* __restrict__ bias)
{
    extern __shared__ __half lsm[];
    const uint32_t ahBase = smem_u32(lsm);
    const uint32_t bhBase = ahBase + LG_BOFF*2;

    const int tid  = threadIdx.x;
    const int lane = tid & 31;
    const int wid  = tid >> 5;
    const int wm   = (wid >> 2) * 64;
    const int wn   = (wid & 3) * 32;
    const int m0   = blockIdx.x * 128;
    const int n0   = blockIdx.y * 128;

    auto fill = [&](int s, int k0) {
        #pragma unroll
        for (int i = 0; i < 2; i++) {
            int id = i*256 + tid;
            int r  = id >> 2;
            int c  = (id & 3) << 3;
            cp_async16(ahBase + (uint32_t)((s*LG_ASTAGE + r*LG_ASTRIDE + c) << 1),
                       A + (long)(m0 + r)*CDIM + k0 + c);
        }
        #pragma unroll
        for (int i = 0; i < 2; i++) {
            int id = i*256 + tid;
            int r  = id >> 4;
            int c  = (id & 15) << 3;
            cp_async16(bhBase + (uint32_t)((s*LG_BSTAGE + r*LG_BSTRIDE + c) << 1),
                       Bh_g + (long)(k0 + r)*VOCAB + n0 + c);
        }
        cp_commit();
    };

    float acc[16][4];
    #pragma unroll
    for (int i = 0; i < 16; i++)
        #pragma unroll
        for (int j = 0; j < 4; j++) acc[i][j] = 0.f;

    fill(0, 0);
    fill(1, 32);

    const int nt = CDIM/32;
    #pragma unroll 1
    for (int kt = 0; kt < nt; kt++) {
        if (kt + 2 < nt) fill((kt + 2) % 3, (kt + 2) * 32);
        int ahead = nt - 1 - kt;
        cp_wait_n(ahead < 2 ? ahead : 2);
        __syncthreads();

        const int buf = kt % 3;
        const uint32_t aBuf = ahBase + (uint32_t)((buf*LG_ASTAGE) << 1);
        const uint32_t bBuf = bhBase + (uint32_t)((buf*LG_BSTAGE) << 1);

        #pragma unroll
        for (int ks = 0; ks < 32; ks += 16) {
            unsigned af[4][4], bf[2][4];
            #pragma unroll
            for (int mt = 0; mt < 4; mt++) {
                int row = wm + mt*16 + (lane & 15);
                int col = ks + ((lane & 16) >> 1);
                ldsm_x4(af[mt], aBuf + (uint32_t)((row*LG_ASTRIDE + col) << 1));
            }
            #pragma unroll
            for (int pr = 0; pr < 2; pr++) {
                int row = ks + (lane & 15);
                int col = wn + pr*16 + ((lane & 16) >> 1);
                ldsm_x4_t(bf[pr], bBuf + (uint32_t)((row*LG_BSTRIDE + col) << 1));
            }
            #pragma unroll
            for (int mt = 0; mt < 4; mt++)
                #pragma unroll
                for (int nt2 = 0; nt2 < 4; nt2++)
                    mma_f16(acc[mt*4 + nt2], af[mt],
                            bf[nt2 >> 1][(nt2 & 1)*2], bf[nt2 >> 1][(nt2 & 1)*2 + 1]);
        }
        __syncthreads();
    }

    const int g  = lane >> 2;
    const int tg = lane & 3;
    #pragma unroll
    for (int nt2 = 0; nt2 < 4; nt2++) {
        int n = n0 + wn + nt2*8 + 2*tg;
        float2 bz = *reinterpret_cast<const float2*>(bias + n);
        #pragma unroll
        for (int mt = 0; mt < 4; mt++) {
            int m = m0 + wm + mt*16 + g;
            float* c = acc[mt*4 + nt2];
            *reinterpret_cast<float2*>(C + (long)m*VOCAB + n)     = make_float2(c[0]+bz.x, c[1]+bz.y);
            *reinterpret_cast<float2*>(C + (long)(m+8)*VOCAB + n) = make_float2(c[2]+bz.x, c[3]+bz.y);
        }
    }
}

// ---------------------------------------------------------------------------
// TF32 small GEMM, 2-stage cp.async, optional fused LayerNorm on A.
// When LN and chout != nullptr: n0==0 blocks also emit the fp16 concat rows.
// ---------------------------------------------------------------------------
template<bool GELU, bool LN>
__global__ __launch_bounds__(128) void tc_gemm(
    int N, int K,
    const float* __restrict__ A, int lda,
    const float* __restrict__ B, int ldb,
    float* __restrict__ C, int ldc,
    const float* __restrict__ bias,
    const float* __restrict__ residual,
    const float* __restrict__ ln_g,
    const float* __restrict__ ln_b,
    __half* __restrict__ chout)
{
    __shared__ float As[2][64][36];
    __shared__ float Bs[2][32][68];
    __shared__ float smean[64];
    __shared__ float srstd[64];
    __shared__ float sg[256];
    __shared__ float sb[256];

    const int tid  = threadIdx.x;
    const int lane = tid & 31;
    const int wid  = tid >> 5;
    const int wm   = (wid >> 1) * 32;
    const int wn   = (wid & 1) * 32;
    const int m0   = blockIdx.y * 64;
    const int n0   = blockIdx.x * 64;
    const int g    = lane >> 2;
    const int tg   = lane & 3;
    const int nt   = K >> 5;

    const uint32_t asBase = smem_u32(&As[0][0][0]);
    const uint32_t bsBase = smem_u32(&Bs[0][0][0]);

    const int a_r  = tid >> 3;
    const int a_c4 = (tid & 7) << 2;
    const int b_r  = tid >> 4;
    const int b_c4 = (tid & 15) << 2;

    auto fill = [&](int s, int k0) {
        #pragma unroll
        for (int i = 0; i < 4; i++) {
            int r = a_r + i*16;
            cp_async16(asBase + (uint32_t)(((s*64 + r)*36 + a_c4) << 2),
                       A + (long)(m0 + r)*lda + k0 + a_c4);
        }
        #pragma unroll
        for (int i = 0; i < 4; i++) {
            int r = b_r + i*8;
            if (n0 + b_c4 < N) {
                cp_async16(bsBase + (uint32_t)(((s*32 + r)*68 + b_c4) << 2),
                           B + (long)(k0 + r)*ldb + n0 + b_c4);
            } else {
                *reinterpret_cast<float4*>(&Bs[s][r][b_c4]) = make_float4(0.f,0.f,0.f,0.f);
            }
        }
        cp_commit();
    };

    fill(0, 0);

    if (LN) {
        int r  = tid >> 1;
        int hf = tid & 1;
        const float* rowp = A + (long)(m0 + r)*lda;
        float s = 0.f, s2 = 0.f;
        for (int i = hf*4; i < K; i += 8) {
            float4 u = *reinterpret_cast<const float4*>(rowp + i);
            s  += u.x + u.y + u.z + u.w;
            s2 += u.x*u.x + u.y*u.y + u.z*u.z + u.w*u.w;
        }
        s  += __shfl_xor_sync(0xffffffffu, s, 1);
        s2 += __shfl_xor_sync(0xffffffffu, s2, 1);
        if (!hf) {
            float inv = 1.f / (float)K;
            float mu  = s * inv;
            float var = s2 * inv - mu*mu;
            smean[r] = mu;
            srstd[r] = rsqrtf(var + 1e-5f);
        }
        if (tid < 64) {
            *reinterpret_cast<float4*>(&sg[tid*4]) = *reinterpret_cast<const float4*>(ln_g + tid*4);
        } else {
            int t = tid - 64;
            *reinterpret_cast<float4*>(&sb[t*4]) = *reinterpret_cast<const float4*>(ln_b + t*4);
        }
        __syncthreads();

        if (chout && blockIdx.x == 0) {
            for (int idx = tid; idx < 64*64; idx += 128) {
                int r2 = idx >> 6;
                int c4 = (idx & 63) << 2;
                float4 u = *reinterpret_cast<const float4*>(A + (long)(m0 + r2)*lda + c4);
                float mu = smean[r2], rs = srstd[r2];
                float4 gm = *reinterpret_cast<const float4*>(&sg[c4]);
                float4 bt = *reinterpret_cast<const float4*>(&sb[c4]);
                __half2 h0 = __floats2half2_rn((u.x - mu)*rs*gm.x + bt.x,
                                               (u.y - mu)*rs*gm.y + bt.y);
                __half2 h1 = __floats2half2_rn((u.z - mu)*rs*gm.z + bt.z,
                                               (u.w - mu)*rs*gm.w + bt.w);
                uint2 o;
                o.x = *reinterpret_cast<unsigned*>(&h0);
                o.y = *reinterpret_cast<unsigned*>(&h1);
                *reinterpret_cast<uint2*>(chout + (long)(m0 + r2)*CDIM + c4) = o;
            }
        }
    }

    float rs_[4], mrs_[4];
    if (LN) {
        #pragma unroll
        for (int q = 0; q < 4; q++) {
            int r = wm + q*8 + g;
            rs_[q]  = srstd[r];
            mrs_[q] = smean[r] * rs_[q];
        }
    }

    float acc[8][4];
    #pragma unroll
    for (int i = 0; i < 8; i++)
        #pragma unroll
        for (int j = 0; j < 4; j++) acc[i][j] = 0.f;

    #pragma unroll 1
    for (int kt = 0; kt < nt; kt++) {
        const bool more = (kt + 1) < nt;
        if (more) fill((kt + 1) & 1, (kt + 1) * 32);
        if (more) cp_wait1(); else cp_wait0();
        __syncthreads();

        const int buf = kt & 1;
        const int k0  = kt * 32;

        #pragma unroll
        for (int ks = 0; ks < 32; ks += 8) {
            unsigned af[2][4], bf[4][2];
            float gm0 = 0.f, gm4 = 0.f, bt0 = 0.f, bt4 = 0.f;
            if (LN) {
                gm0 = sg[k0 + ks + tg];   gm4 = sg[k0 + ks + tg + 4];
                bt0 = sb[k0 + ks + tg];   bt4 = sb[k0 + ks + tg + 4];
            }
            #pragma unroll
            for (int mt = 0; mt < 2; mt++) {
                int mr = wm + mt*16 + g;
                float r00 = As[buf][mr  ][ks + tg    ];
                float r10 = As[buf][mr+8][ks + tg    ];
                float r04 = As[buf][mr  ][ks + tg + 4];
                float r14 = As[buf][mr+8][ks + tg + 4];
                if (LN) {
                    float rsa = rs_[mt*2],   ma = mrs_[mt*2];
                    float rsb = rs_[mt*2+1], mb = mrs_[mt*2+1];
                    r00 = fmaf(fmaf(r00, rsa, -ma), gm0, bt0);
                    r10 = fmaf(fmaf(r10, rsb, -mb), gm0, bt0);
                    r04 = fmaf(fmaf(r04, rsa, -ma), gm4, bt4);
                    r14 = fmaf(fmaf(r14, rsb, -mb), gm4, bt4);
                }
                af[mt][0] = f2tf32(r00);
                af[mt][1] = f2tf32(r10);
                af[mt][2] = f2tf32(r04);
                af[mt][3] = f2tf32(r14);
            }
            #pragma unroll
            for (int nt2 = 0; nt2 < 4; nt2++) {
                int nc = wn + nt2*8 + g;
                bf[nt2][0] = f2tf32(Bs[buf][ks + tg    ][nc]);
                bf[nt2][1] = f2tf32(Bs[buf][ks + tg + 4][nc]);
            }
            #pragma unroll
            for (int mt = 0; mt < 2; mt++)
                #pragma unroll
                for (int nt2 = 0; nt2 < 4; nt2++)
                    mma_tf32(acc[mt*4 + nt2], af[mt], bf[nt2]);
        }
        __syncthreads();
    }

    #pragma unroll
    for (int nt2 = 0; nt2 < 4; nt2++) {
        int n = n0 + wn + nt2*8 + 2*tg;
        if (n < N) {
            float2 bz = make_float2(0.f, 0.f);
            if (bias) bz = *reinterpret_cast<const float2*>(bias + n);
            #pragma unroll
            for (int mt = 0; mt < 2; mt++) {
                int m = m0 + wm + mt*16 + g;
                float* c = acc[mt*4 + nt2];
                float v[4] = {c[0]+bz.x, c[1]+bz.y, c[2]+bz.x, c[3]+bz.y};
                if (GELU) {
                    #pragma unroll
                    for (int q = 0; q < 4; q++) {
                        float u = v[q];
                        float tt = 0.7978845608028654f * (u + 0.044715f*u*u*u);
                        v[q] = 0.5f*u*(1.f + tanhf(tt));
                    }
                }
                if (residual) {
                    float2 r0 = *reinterpret_cast<const float2*>(residual + (long)m*ldc + n);
                    float2 r1 = *reinterpret_cast<const float2*>(residual + (long)(m+8)*ldc + n);
                    v[0] += r0.x; v[1] += r0.y; v[2] += r1.x; v[3] += r1.y;
                }
                *reinterpret_cast<float2*>(C + (long)m*ldc + n)     = make_float2(v[0], v[1]);
                *reinterpret_cast<float2*>(C + (long)(m+8)*ldc + n) = make_float2(v[2], v[3]);
            }
        }
    }
}

// ---------------------------------------------------------------------------
// TF32 tiny-tile GEMM (Wo, FF2): 32x32 tile, BK=32, 4-stage cp.async.
// ---------------------------------------------------------------------------
__global__ __launch_bounds__(128) void tc_gemm_small(
    int N, int K,
    const float* __restrict__ A, int lda,
    const float* __restrict__ B, int ldb,
    float* __restrict__ C, int ldc,
    const float* __restrict__ bias,
    const float* __restrict__ residual)
{
    __shared__ float As[4][32][36];
    __shared__ float Bs[4][32][36];

    const int tid  = threadIdx.x;
    const int lane = tid & 31;
    const int wid  = tid >> 5;
    const int wm   = (wid >> 1) * 16;
    const int wn   = (wid & 1) * 16;
    const int m0   = blockIdx.y * 32;
    const int n0   = blockIdx.x * 32;
    const int g    = lane >> 2;
    const int tg   = lane & 3;
    const int nt   = K >> 5;

    const uint32_t asBase = smem_u32(&As[0][0][0]);
    const uint32_t bsBase = smem_u32(&Bs[0][0][0]);
    const int r_  = tid >> 3;
    const int c4  = (tid & 7) << 2;

    auto fill = [&](int s, int k0) {
        #pragma unroll
        for (int i = 0; i < 2; i++) {
            int r = r_ + i*16;
            cp_async16(asBase + (uint32_t)(((s*32 + r)*36 + c4) << 2),
                       A + (long)(m0 + r)*lda + k0 + c4);
            cp_async16(bsBase + (uint32_t)(((s*32 + r)*36 + c4) << 2),
                       B + (long)(k0 + r)*ldb + n0 + c4);
        }
        cp_commit();
    };

    const int pre = (nt < 3) ? nt : 3;
    for (int s = 0; s < pre; s++) fill(s, s*32);

    float acc[2][4];
    #pragma unroll
    for (int i = 0; i < 2; i++)
        #pragma unroll
        for (int j = 0; j < 4; j++) acc[i][j] = 0.f;

    #pragma unroll 1
    for (int kt = 0; kt < nt; kt++) {
        if (kt + 3 < nt) fill((kt + 3) & 3, (kt + 3) * 32);
        int ahead = nt - 1 - kt;
        cp_wait_n(ahead < 3 ? ahead : 3);
        __syncthreads();

        const int buf = kt & 3;
        #pragma unroll
        for (int ks = 0; ks < 32; ks += 8) {
            unsigned af[4], bf[2][2];
            af[0] = f2tf32(As[buf][wm + g    ][ks + tg    ]);
            af[1] = f2tf32(As[buf][wm + g + 8][ks + tg    ]);
            af[2] = f2tf32(As[buf][wm + g    ][ks + tg + 4]);
            af[3] = f2tf32(As[buf][wm + g + 8][ks + tg + 4]);
            #pragma unroll
            for (int nt2 = 0; nt2 < 2; nt2++) {
                int nc = wn + nt2*8 + g;
                bf[nt2][0] = f2tf32(Bs[buf][ks + tg    ][nc]);
                bf[nt2][1] = f2tf32(Bs[buf][ks + tg + 4][nc]);
            }
            #pragma unroll
            for (int nt2 = 0; nt2 < 2; nt2++)
                mma_tf32(acc[nt2], af, bf[nt2]);
        }
        __syncthreads();
    }

    #pragma unroll
    for (int nt2 = 0; nt2 < 2; nt2++) {
        int n = n0 + wn + nt2*8 + 2*tg;
        float2 bz = make_float2(0.f, 0.f);
        if (bias) bz = *reinterpret_cast<const float2*>(bias + n);
        int m = m0 + wm + g;
        float* c = acc[nt2];
        float v[4] = {c[0]+bz.x, c[1]+bz.y, c[2]+bz.x, c[3]+bz.y};
        if (residual) {
            float2 r0 = *reinterpret_cast<const float2*>(residual + (long)m*ldc + n);
            float2 r1 = *reinterpret_cast<const float2*>(residual + (long)(m+8)*ldc + n);
            v[0] += r0.x; v[1] += r0.y; v[2] += r1.x; v[3] += r1.y;
        }
        *reinterpret_cast<float2*>(C + (long)m*ldc + n)     = make_float2(v[0], v[1]);
        *reinterpret_cast<float2*>(C + (long)(m+8)*ldc + n) = make_float2(v[2], v[3]);
    }
}

// ---------------------------------------------------------------------------
// Causal attention: block = (head, batch, q-chunk of 16). 256 blocks.
// q = tid>>3 (16 queries), j = tid&7 (8 lanes/query).
// Ps stride 132 (16B-aligned) -> float4 reads; V read as float4.
// ---------------------------------------------------------------------------
#define QC 16
__global__ __launch_bounds__(128) void attention_kernel(
    const float* __restrict__ qkv, float* __restrict__ att_out)
{
    __shared__ float Ks[TT][36];
    __shared__ float Vs[TT][32];
    __shared__ __align__(16) float Ps[QC][132];
    const int h  = blockIdx.x;
    const int b  = blockIdx.y;
    const int qc = blockIdx.z;
    const int tid = threadIdx.x;
    const float scale = 0.17677669529663687f;

    {
        const float* kp = qkv + (long)(b*TT + tid)*(3*DD) + DD + h*HD_ATT;
        const float* vp = kp + DD;
        #pragma unroll
        for (int d = 0; d < 32; d += 4) {
            *reinterpret_cast<float4*>(&Ks[tid][d]) = *reinterpret_cast<const float4*>(kp + d);
            *reinterpret_cast<float4*>(&Vs[tid][d]) = *reinterpret_cast<const float4*>(vp + d);
        }
    }
    __syncthreads();

    const int q = tid >> 3;          // 0..15
    const int j = tid & 7;           // 0..7
    const int qglob = qc*QC + q;

    float qv[32];
    {
        const float* qp = qkv + (long)(b*TT + qglob)*(3*DD) + h*HD_ATT;
        #pragma unroll
        for (int d = 0; d < 32; d += 4) {
            float4 t = *reinterpret_cast<const float4*>(qp + d);
            qv[d]=t.x; qv[d+1]=t.y; qv[d+2]=t.z; qv[d+3]=t.w;
        }
    }

    float s[16];
    float mmax = -1e30f;
    #pragma unroll
    for (int kk = 0; kk < 16; kk++) {
        int k = kk*8 + j;
        float acc = 0.f;
        #pragma unroll
        for (int d = 0; d < 32; d += 4) {
            float4 kv = *reinterpret_cast<const float4*>(&Ks[k][d]);
            acc += qv[d]*kv.x + qv[d+1]*kv.y + qv[d+2]*kv.z + qv[d+3]*kv.w;
        }
        s[kk] = (k <= qglob) ? acc*scale : -1e30f;
        mmax = fmaxf(mmax, s[kk]);
    }
    #pragma unroll
    for (int o = 1; o < 8; o <<= 1)
        mmax = fmaxf(mmax, __shfl_xor_sync(0xffffffffu, mmax, o));

    float l = 0.f;
    #pragma unroll
    for (int kk = 0; kk < 16; kk++) {
        float p = __expf(s[kk] - mmax);
        l += p;
        Ps[q][kk*8 + j] = p;
    }
    #pragma unroll
    for (int o = 1; o < 8; o <<= 1)
        l += __shfl_xor_sync(0xffffffffu, l, o);
    float linv = 1.f / l;
    __syncthreads();

    // output dims j*4 .. j*4+3, float4 Ps + float4 V
    float ox=0.f, oy=0.f, oz=0.f, ow=0.f;
    #pragma unroll 4
    for (int k = 0; k < TT; k += 4) {
        float4 p4 = *reinterpret_cast<const float4*>(&Ps[q][k]);
        float4 v0 = *reinterpret_cast<const float4*>(&Vs[k  ][j*4]);
        float4 v1 = *reinterpret_cast<const float4*>(&Vs[k+1][j*4]);
        float4 v2 = *reinterpret_cast<const float4*>(&Vs[k+2][j*4]);
        float4 v3 = *reinterpret_cast<const float4*>(&Vs[k+3][j*4]);
        ox += p4.x*v0.x + p4.y*v1.x + p4.z*v2.x + p4.w*v3.x;
        oy += p4.x*v0.y + p4.y*v1.y + p4.z*v2.y + p4.w*v3.y;
        oz += p4.x*v0.z + p4.y*v1.z + p4.z*v2.z + p4.w*v3.z;
        ow += p4.x*v0.w + p4.y*v1.w + p4.z*v2.w + p4.w*v3.w;
    }
    float4 o4 = make_float4(ox*linv, oy*linv, oz*linv, ow*linv);
    *reinterpret_cast<float4*>(att_out + (long)(b*TT + qglob)*DD + h*HD_ATT + j*4) = o4;
}

// ---------------------------------------------------------------------------
// Memory scan (collapsed; see derivation R2).  fma.rn.f32x2 GEMV, 4 accs.
// ---------------------------------------------------------------------------
__global__ __launch_bounds__(320) void scan_kernel(
    const float* __restrict__ Hif,
    const float* __restrict__ W_iface,
    __half* __restrict__ ch)
{
    int b   = blockIdx.x;
    int tid = threadIdx.x;
    __shared__ __align__(16) float rv_s[MD];
    __shared__ float m_s[MD];
    __shared__ float if_s[260];

    unsigned long long w2[64];
    int gcol = 0;
    if (tid < 260) {
        gcol = (tid/65)*129 + 64 + (tid%65);
        #pragma unroll
        for (int k = 0; k < 64; k++) {
            float lo = W_iface[(long)(256 + 2*k    )*IFACE + gcol];
            float hi = W_iface[(long)(256 + 2*k + 1)*IFACE + gcol];
            asm("mov.b64 %0, {%1,%2};" : "=l"(w2[k]) : "f"(lo), "f"(hi));
        }
    }
    if (tid < MD) { rv_s[tid] = 0.f; m_s[tid] = 0.f; }
    __syncthreads();

    const unsigned long long* rv2 = reinterpret_cast<const unsigned long long*>(rv_s);

    for (int t = 0; t < TT; t++) {
        if (tid < MD)
            ch[(long)(b*TT + t)*CDIM + DD + tid] = __float2half(rv_s[tid]);
        if (tid < 260) {
            float hbase = Hif[(long)(b*TT + t)*IFACE + gcol];
            unsigned long long a0 = 0ull, a1 = 0ull, a2 = 0ull, a3 = 0ull;
            #pragma unroll
            for (int k = 0; k < 64; k += 4) {
                asm("fma.rn.f32x2 %0, %1, %2, %0;" : "+l"(a0) : "l"(rv2[k  ]), "l"(w2[k  ]));
                asm("fma.rn.f32x2 %0, %1, %2, %0;" : "+l"(a1) : "l"(rv2[k+1]), "l"(w2[k+1]));
                asm("fma.rn.f32x2 %0, %1, %2, %0;" : "+l"(a2) : "l"(rv2[k+2]), "l"(w2[k+2]));
                asm("fma.rn.f32x2 %0, %1, %2, %0;" : "+l"(a3) : "l"(rv2[k+3]), "l"(w2[k+3]));
            }
            float l0, h0, l1, h1, l2, h2, l3, h3;
            asm("mov.b64 {%0,%1}, %2;" : "=f"(l0), "=f"(h0) : "l"(a0));
            asm("mov.b64 {%0,%1}, %2;" : "=f"(l1), "=f"(h1) : "l"(a1));
            asm("mov.b64 {%0,%1}, %2;" : "=f"(l2), "=f"(h2) : "l"(a2));
            asm("mov.b64 {%0,%1}, %2;" : "=f"(l3), "=f"(h3) : "l"(a3));
            if_s[tid] = hbase + ((l0 + h0) + (l1 + h1)) + ((l2 + h2) + (l3 + h3));
        }
        __syncthreads();
        if (tid < MD) {
            int hh = tid >> 5;
            int d  = tid & 31;
            int base = hh*65;
            float wv = if_s[base + d];
            float er = 1.f / (1.f + __expf(-if_s[base + 32 + d]));
            float ag = 1.f / (1.f + __expf(-if_s[base + 64]));
            float mo = m_s[tid];
            rv_s[tid] = rv_s[tid] + mo;
            m_s[tid]  = mo * (1.f - er*(1.f/512.f)) + (ag*(1.f/512.f))*wv;
        }
        __syncthreads();
    }
}

// ---------------------------------------------------------------------------
// Launch
// ---------------------------------------------------------------------------
extern "C" void kernel_launch(void* const* d_in, const int* in_sizes, int n_in,
                              void* d_out, int out_size)
{
    const int*   seq   = (const int*)  d_in[0];
    const float* tok   = (const float*)d_in[1];
    const float* pos   = (const float*)d_in[2];
    const float* Wqkv  = (const float*)d_in[3];
    const float* Wo    = (const float*)d_in[4];
    const float* ln1g  = (const float*)d_in[5];
    const float* ln1b  = (const float*)d_in[6];
    const float* ln2g  = (const float*)d_in[7];
    const float* ln2b  = (const float*)d_in[8];
    const float* W1    = (const float*)d_in[9];
    const float* b1    = (const float*)d_in[10];
    const float* W2    = (const float*)d_in[11];
    const float* b2    = (const float*)d_in[12];
    const float* lnfg  = (const float*)d_in[13];
    const float* lnfb  = (const float*)d_in[14];
    const float* Wlog  = (const float*)d_in[15];
    const float* blog  = (const float*)d_in[16];
    const float* Wif   = (const float*)d_in[17];
    const float* bif   = (const float*)d_in[18];
    float* out = (float*)d_out;

    float *gx, *gqkv, *gatt, *gff, *gHif;
    __half *gch, *gwlh;
    cudaGetSymbolAddress((void**)&gx,   g_x);
    cudaGetSymbolAddress((void**)&gqkv, g_qkv);
    cudaGetSymbolAddress((void**)&gatt, g_att);
    cudaGetSymbolAddress((void**)&gff,  g_ff);
    cudaGetSymbolAddress((void**)&gHif, g_Hif);
    cudaGetSymbolAddress((void**)&gch,  g_ch);
    cudaGetSymbolAddress((void**)&gwlh, g_wlh);

    static bool init_done = false;
    static cudaStream_t s2;
    static cudaEvent_t evFork, evJoin;
    if (!init_done) {
        cudaFuncSetAttribute(logits_f16_kernel,
                             cudaFuncAttributeMaxDynamicSharedMemorySize,
                             LG_SMEM_BYTES);
        cudaStreamCreateWithFlags(&s2, cudaStreamNonBlocking);
        cudaEventCreateWithFlags(&evFork, cudaEventDisableTiming);
        cudaEventCreateWithFlags(&evJoin, cudaEventDisableTiming);
        init_done = true;
    }

    // Fork: wconv runs on side stream, concurrent with the transformer chain.
    cudaEventRecord(evFork, 0);
    cudaStreamWaitEvent(s2, evFork, 0);
    wconv_kernel<<<(CDIM*VOCAB)/1024, 256, 0, s2>>>(Wlog, gwlh);
    cudaEventRecord(evJoin, s2);

    embed_kernel<<<BT, DD>>>(seq, tok, pos, gx);

    for (int l = 0; l < 2; l++) {
        tc_gemm<false, true><<<dim3(12, 8), 128>>>(
            3*DD, DD, gx, DD, Wqkv + (long)l*DD*3*DD, 3*DD,
            gqkv, 3*DD, nullptr, nullptr, ln1g + l*DD, ln1b + l*DD, nullptr);
        attention_kernel<<<dim3(NH, BB, TT/QC), 128>>>(gqkv, gatt);
        tc_gemm_small<<<dim3(8, 16), 128>>>(
            DD, DD, gatt, DD, Wo + (long)l*DD*DD, DD,
            gx, DD, nullptr, gx);
        tc_gemm<true, true><<<dim3(16, 8), 128>>>(
            FF_, DD, gx, DD, W1 + (long)l*DD*FF_, FF_,
            gff, FF_, b1 + l*FF_, nullptr, ln2g + l*DD, ln2b + l*DD, nullptr);
        tc_gemm_small<<<dim3(8, 16), 128>>>(
            DD, FF_, gff, FF_, W2 + (long)l*FF_*DD, DD,
            gx, DD, b2 + l*DD, gx);
    }

    tc_gemm<false, true><<<dim3((IFACE + 63)/64, 8), 128>>>(
        IFACE, DD, gx, DD, Wif, IFACE, gHif, IFACE, bif, nullptr,
        lnfg, lnfb, gch);

    scan_kernel<<<BB, 320>>>(gHif, Wif, gch);

    // Join: logits needs gwlh from the side stream.
    cudaStreamWaitEvent(0, evJoin, 0);
    logits_f16_kernel<<<dim3(4, VOCAB/128), 256, LG_SMEM_BYTES>>>(gch, gwlh, out, blog);
}